// round 1
// baseline (speedup 1.0000x reference)
#include <cuda_runtime.h>
#include <math.h>

#define Bb   8
#define Nn   576
#define Dd   512
#define Mm   16
#define Hh   8
#define BN   (Bb*Nn)      // 4608
#define KTOP 51

// ---- scratch (static device globals; no allocation) ----
__device__ float g_qkv [BN * 3 * Dd];   // 28.3 MB
__device__ float g_attn[BN * Dd];       // 9.4 MB
__device__ float g_fenh[BN * Dd];
__device__ float g_h   [BN * Dd];
__device__ float g_comp[BN * Mm];

// ============================================================
// SGEMM: C[M,N] = A[M,K] * B[N,K]^T + bias[N] (+ residual[M,N])
// A row-major lda=K, B row-major ldb=K (weight layout [out,in]).
// Tile 128x128, 256 threads, 8x8 micro-tile, K-chunk 16.
// All problem dims divide evenly -> no bounds checks.
// ============================================================
__global__ __launch_bounds__(256) void sgemm_tn(
    const float* __restrict__ A, const float* __restrict__ B,
    const float* __restrict__ bias, const float* __restrict__ residual,
    float* __restrict__ C, int K, int N)
{
    __shared__ float As[16][132];
    __shared__ float Bs[16][132];
    const int tid = threadIdx.x;
    const int ty = tid >> 4, tx = tid & 15;
    const int rowBase = blockIdx.y * 128;
    const int colBase = blockIdx.x * 128;

    float acc[8][8];
    #pragma unroll
    for (int i = 0; i < 8; i++)
        #pragma unroll
        for (int j = 0; j < 8; j++) acc[i][j] = 0.f;

    for (int k0 = 0; k0 < K; k0 += 16) {
        #pragma unroll
        for (int it = 0; it < 2; it++) {
            int f  = tid + it * 256;        // 0..511 float4 slots
            int r  = f >> 2;                // 0..127
            int kq = (f & 3) << 2;          // 0,4,8,12
            float4 av = *reinterpret_cast<const float4*>(
                A + (size_t)(rowBase + r) * K + k0 + kq);
            As[kq + 0][r] = av.x; As[kq + 1][r] = av.y;
            As[kq + 2][r] = av.z; As[kq + 3][r] = av.w;
            float4 bv = *reinterpret_cast<const float4*>(
                B + (size_t)(colBase + r) * K + k0 + kq);
            Bs[kq + 0][r] = bv.x; Bs[kq + 1][r] = bv.y;
            Bs[kq + 2][r] = bv.z; Bs[kq + 3][r] = bv.w;
        }
        __syncthreads();
        #pragma unroll
        for (int kk = 0; kk < 16; kk++) {
            float a[8], bb[8];
            float4 a0 = *reinterpret_cast<const float4*>(&As[kk][ty * 8]);
            float4 a1 = *reinterpret_cast<const float4*>(&As[kk][ty * 8 + 4]);
            float4 b0 = *reinterpret_cast<const float4*>(&Bs[kk][tx * 8]);
            float4 b1 = *reinterpret_cast<const float4*>(&Bs[kk][tx * 8 + 4]);
            a[0]=a0.x; a[1]=a0.y; a[2]=a0.z; a[3]=a0.w;
            a[4]=a1.x; a[5]=a1.y; a[6]=a1.z; a[7]=a1.w;
            bb[0]=b0.x; bb[1]=b0.y; bb[2]=b0.z; bb[3]=b0.w;
            bb[4]=b1.x; bb[5]=b1.y; bb[6]=b1.z; bb[7]=b1.w;
            #pragma unroll
            for (int i = 0; i < 8; i++)
                #pragma unroll
                for (int j = 0; j < 8; j++)
                    acc[i][j] += a[i] * bb[j];
        }
        __syncthreads();
    }

    #pragma unroll
    for (int i = 0; i < 8; i++) {
        int r = rowBase + ty * 8 + i;
        #pragma unroll
        for (int j = 0; j < 8; j++) {
            int c = colBase + tx * 8 + j;
            float v = acc[i][j];
            if (bias)     v += bias[c];
            if (residual) v += residual[(size_t)r * N + c];
            C[(size_t)r * N + c] = v;
        }
    }
}

// ============================================================
// Fused attention: flash-style, per (b,h), 64-query tiles,
// 32-key chunks, online softmax. qkv layout: [BN][1536],
// q cols [0,512), k [512,1024), v [1024,1536); head h -> +h*64.
// Block: 256 threads (ty 0..15 -> 4 query rows each; tx 0..15).
// ============================================================
__global__ __launch_bounds__(256) void attn_kernel(
    const float* __restrict__ qkv, float* __restrict__ out)
{
    __shared__ float Qs[64][65];
    __shared__ float Ks[32][65];
    __shared__ float Vs[32][65];
    __shared__ float Ss[64][33];

    const int tid = threadIdx.x;
    const int ty = tid >> 4, tx = tid & 15;
    const int bh = blockIdx.y;
    const int b = bh >> 3, h = bh & 7;
    const int q0 = blockIdx.x * 64;
    const float scale = 0.125f;  // 1/sqrt(64)

    const float* qbase = qkv + (size_t)(b * Nn + q0) * 1536 + h * 64;
    // load Q tile (scaled), float4
    #pragma unroll
    for (int it = 0; it < 4; it++) {
        int f = tid + it * 256;          // 0..1023 float4 slots
        int r = f >> 4;                  // 0..63
        int c = (f & 15) << 2;           // 0..60
        float4 v = *reinterpret_cast<const float4*>(qbase + (size_t)r * 1536 + c);
        Qs[r][c + 0] = v.x * scale; Qs[r][c + 1] = v.y * scale;
        Qs[r][c + 2] = v.z * scale; Qs[r][c + 3] = v.w * scale;
    }

    float m_i[4], l_i[4], acc[4][4];
    #pragma unroll
    for (int i = 0; i < 4; i++) {
        m_i[i] = -1e30f; l_i[i] = 0.f;
        #pragma unroll
        for (int j = 0; j < 4; j++) acc[i][j] = 0.f;
    }

    const float* kbase = qkv + (size_t)(b * Nn) * 1536 + 512  + h * 64;
    const float* vbase = qkv + (size_t)(b * Nn) * 1536 + 1024 + h * 64;

    for (int kc = 0; kc < Nn; kc += 32) {
        __syncthreads();  // protect Ks/Vs/Ss from previous iteration
        #pragma unroll
        for (int it = 0; it < 2; it++) {
            int f = tid + it * 256;      // 0..511 float4 slots
            int r = f >> 4;              // 0..31
            int c = (f & 15) << 2;
            float4 kv = *reinterpret_cast<const float4*>(kbase + (size_t)(kc + r) * 1536 + c);
            Ks[r][c+0]=kv.x; Ks[r][c+1]=kv.y; Ks[r][c+2]=kv.z; Ks[r][c+3]=kv.w;
            float4 vv = *reinterpret_cast<const float4*>(vbase + (size_t)(kc + r) * 1536 + c);
            Vs[r][c+0]=vv.x; Vs[r][c+1]=vv.y; Vs[r][c+2]=vv.z; Vs[r][c+3]=vv.w;
        }
        __syncthreads();

        // S tile: rows 4ty+i, cols 2tx+j
        float s[4][2];
        #pragma unroll
        for (int i = 0; i < 4; i++) { s[i][0] = 0.f; s[i][1] = 0.f; }
        #pragma unroll
        for (int kk = 0; kk < 64; kk++) {
            float k0v = Ks[2 * tx][kk];
            float k1v = Ks[2 * tx + 1][kk];
            #pragma unroll
            for (int i = 0; i < 4; i++) {
                float a = Qs[4 * ty + i][kk];
                s[i][0] += a * k0v;
                s[i][1] += a * k1v;
            }
        }

        // online softmax (row reduction over 16 tx lanes)
        #pragma unroll
        for (int i = 0; i < 4; i++) {
            float mx = fmaxf(s[i][0], s[i][1]);
            #pragma unroll
            for (int o = 8; o >= 1; o >>= 1)
                mx = fmaxf(mx, __shfl_xor_sync(0xffffffffu, mx, o));
            float mnew = fmaxf(m_i[i], mx);
            float corr = __expf(m_i[i] - mnew);
            float p0 = __expf(s[i][0] - mnew);
            float p1 = __expf(s[i][1] - mnew);
            float ps = p0 + p1;
            #pragma unroll
            for (int o = 8; o >= 1; o >>= 1)
                ps += __shfl_xor_sync(0xffffffffu, ps, o);
            l_i[i] = l_i[i] * corr + ps;
            m_i[i] = mnew;
            #pragma unroll
            for (int j = 0; j < 4; j++) acc[i][j] *= corr;
            Ss[4 * ty + i][2 * tx]     = p0;
            Ss[4 * ty + i][2 * tx + 1] = p1;
        }
        __syncthreads();

        // acc += P * V  (output dims 4tx+j)
        #pragma unroll
        for (int kk = 0; kk < 32; kk++) {
            #pragma unroll
            for (int i = 0; i < 4; i++) {
                float p = Ss[4 * ty + i][kk];
                #pragma unroll
                for (int j = 0; j < 4; j++)
                    acc[i][j] += p * Vs[kk][4 * tx + j];
            }
        }
    }

    float* obase = out + (size_t)(b * Nn + q0) * Dd + h * 64;
    #pragma unroll
    for (int i = 0; i < 4; i++) {
        float inv = 1.f / l_i[i];
        #pragma unroll
        for (int j = 0; j < 4; j++)
            obase[(size_t)(4 * ty + i) * Dd + 4 * tx + j] = acc[i][j] * inv;
    }
}

// ============================================================
// Fused LayerNorm -> exact GELU -> components = h @ w2^T + b2
// One block (256 thr) per row of 512.
// ============================================================
__global__ __launch_bounds__(256) void ln_gelu_comp_kernel(
    const float* __restrict__ h,
    const float* __restrict__ ln_g, const float* __restrict__ ln_b,
    const float* __restrict__ w2,  const float* __restrict__ b2,
    float* __restrict__ comp)
{
    __shared__ float s[512];
    __shared__ float rs[8], rq[8];
    __shared__ float ps[16][17];

    const int row = blockIdx.x, tid = threadIdx.x;
    float x0 = h[(size_t)row * 512 + tid];
    float x1 = h[(size_t)row * 512 + 256 + tid];
    s[tid] = x0; s[tid + 256] = x1;
    float sum = x0 + x1, sq = x0 * x0 + x1 * x1;
    #pragma unroll
    for (int o = 16; o >= 1; o >>= 1) {
        sum += __shfl_xor_sync(0xffffffffu, sum, o);
        sq  += __shfl_xor_sync(0xffffffffu, sq,  o);
    }
    if ((tid & 31) == 0) { rs[tid >> 5] = sum; rq[tid >> 5] = sq; }
    __syncthreads();
    if (tid == 0) {
        float S = 0.f, Q = 0.f;
        #pragma unroll
        for (int i = 0; i < 8; i++) { S += rs[i]; Q += rq[i]; }
        rs[0] = S * (1.f / 512.f);
        rq[0] = Q * (1.f / 512.f);
    }
    __syncthreads();
    const float mean = rs[0];
    const float var  = rq[0] - mean * mean;
    const float rstd = rsqrtf(var + 1e-5f);

    #pragma unroll
    for (int e = tid; e < 512; e += 256) {
        float x = (s[e] - mean) * rstd * ln_g[e] + ln_b[e];
        s[e] = 0.5f * x * (1.f + erff(x * 0.70710678118f));
    }
    __syncthreads();

    const int m = tid & 15, ch = tid >> 4;
    float p = 0.f;
    const float* wrow = w2 + m * 512 + ch * 32;
    const float* srow = &s[ch * 32];
    #pragma unroll
    for (int e = 0; e < 32; e++) p += srow[e] * wrow[e];
    ps[ch][m] = p;
    __syncthreads();
    if (tid < 16) {
        float v = b2[tid];
        #pragma unroll
        for (int c = 0; c < 16; c++) v += ps[c][tid];
        comp[(size_t)row * 16 + tid] = v;
    }
}

// ============================================================
// Outer product + top-51 sparsify + coalesced [D,M] write.
// One block per (b,n): 512 threads = 16 warps; warp w owns m=w.
// Radix-select over uint key = bits(|q|) (monotone for abs floats).
// ============================================================
__global__ __launch_bounds__(512) void outer_topk_kernel(
    const float* __restrict__ F, const float* __restrict__ templates,
    const float* __restrict__ comp, float* __restrict__ out)
{
    __shared__ float Frow[512];
    __shared__ float cs[16];
    __shared__ float Qout[512 * 17];   // padded [d][m]

    const int row = blockIdx.x;
    const int tid = threadIdx.x;
    const int m = tid >> 5, lid = tid & 31;

    Frow[tid] = F[(size_t)row * 512 + tid];
    if (tid < 16) cs[tid] = comp[(size_t)row * 16 + tid];
    __syncthreads();

    const float c = cs[m];
    float    qv[16];
    unsigned key[16];
    #pragma unroll
    for (int i = 0; i < 16; i++) {
        int d = lid + 32 * i;
        float q = Frow[d] * templates[m * 512 + d] * c;
        qv[i]  = q;
        key[i] = __float_as_uint(fabsf(q));
    }

    // find 51st-largest key: maximize prefix s.t. count(key >= prefix) >= 51
    unsigned prefix = 0;
    for (int bit = 30; bit >= 0; bit--) {
        unsigned test = prefix | (1u << bit);
        int cnt = 0;
        #pragma unroll
        for (int i = 0; i < 16; i++) cnt += (key[i] >= test);
        cnt = __reduce_add_sync(0xffffffffu, cnt);
        if (cnt >= KTOP) prefix = test;
    }

    #pragma unroll
    for (int i = 0; i < 16; i++) {
        int d = lid + 32 * i;
        Qout[d * 17 + m] = (key[i] >= prefix) ? qv[i] : 0.f;
    }
    __syncthreads();

    float* ob = out + (size_t)row * (512 * 16);
    #pragma unroll
    for (int i = 0; i < 16; i++) {
        int e = tid + 512 * i;
        ob[e] = Qout[(e >> 4) * 17 + (e & 15)];
    }
}

// ============================================================
extern "C" void kernel_launch(void* const* d_in, const int* in_sizes, int n_in,
                              void* d_out, int out_size) {
    const float* F    = (const float*)d_in[0];
    const float* Wqkv = (const float*)d_in[1];
    const float* bqkv = (const float*)d_in[2];
    const float* Wout = (const float*)d_in[3];
    const float* bout = (const float*)d_in[4];
    const float* w1   = (const float*)d_in[5];
    const float* b1   = (const float*)d_in[6];
    const float* lng  = (const float*)d_in[7];
    const float* lnb  = (const float*)d_in[8];
    const float* w2   = (const float*)d_in[9];
    const float* b2   = (const float*)d_in[10];
    const float* tmpl = (const float*)d_in[11];
    float* out = (float*)d_out;

    float *qkv, *attn, *fenh, *hbuf, *comp;
    cudaGetSymbolAddress((void**)&qkv,  g_qkv);
    cudaGetSymbolAddress((void**)&attn, g_attn);
    cudaGetSymbolAddress((void**)&fenh, g_fenh);
    cudaGetSymbolAddress((void**)&hbuf, g_h);
    cudaGetSymbolAddress((void**)&comp, g_comp);

    // 1) qkv = F @ Wqkv^T + bqkv          [4608 x 1536]
    sgemm_tn<<<dim3(1536 / 128, BN / 128), 256>>>(F, Wqkv, bqkv, nullptr, qkv, 512, 1536);
    // 2) fused attention                   -> attn [4608 x 512]
    attn_kernel<<<dim3(Nn / 64, Bb * Hh), 256>>>(qkv, attn);
    // 3) fenh = F + attn @ Wout^T + bout
    sgemm_tn<<<dim3(512 / 128, BN / 128), 256>>>(attn, Wout, bout, F, fenh, 512, 512);
    // 4) h = fenh @ w1^T + b1
    sgemm_tn<<<dim3(512 / 128, BN / 128), 256>>>(fenh, w1, b1, nullptr, hbuf, 512, 512);
    // 5) LN -> GELU -> comp = h @ w2^T + b2
    ln_gelu_comp_kernel<<<BN, 256>>>(hbuf, lng, lnb, w2, b2, comp);
    // 6) outer product + top-51 + write [B,N,D,M]
    outer_topk_kernel<<<BN, 512>>>(F, tmpl, comp, out);
}

// round 2
// speedup vs baseline: 1.1238x; 1.1238x over previous
#include <cuda_runtime.h>
#include <math.h>

#define Bb   8
#define Nn   576
#define Dd   512
#define Mm   16
#define Hh   8
#define BN   (Bb*Nn)      // 4608
#define KTOP 51

typedef unsigned long long u64;

// ---- packed fp32x2 helpers (sm_103a FFMA2 path; ptxas never auto-fuses) ----
__device__ __forceinline__ u64 pack2(float lo, float hi) {
    u64 r; asm("mov.b64 %0, {%1, %2};" : "=l"(r) : "f"(lo), "f"(hi)); return r;
}
__device__ __forceinline__ u64 splat2(float x) {
    u64 r; asm("mov.b64 %0, {%1, %1};" : "=l"(r) : "f"(x)); return r;
}
__device__ __forceinline__ void fma2(u64& d, u64 a, u64 b) {
    asm("fma.rn.f32x2 %0, %1, %2, %3;" : "=l"(d) : "l"(a), "l"(b), "l"(d));
}
__device__ __forceinline__ u64 mul2(u64 a, u64 b) {
    u64 d; asm("mul.rn.f32x2 %0, %1, %2;" : "=l"(d) : "l"(a), "l"(b)); return d;
}
__device__ __forceinline__ float2 unpack2(u64 v) {
    float2 f; asm("mov.b64 {%0, %1}, %2;" : "=f"(f.x), "=f"(f.y) : "l"(v)); return f;
}

// ---- scratch (static device globals; no allocation) ----
__device__ float g_qkv [BN * 3 * Dd];
__device__ float g_attn[BN * Dd];
__device__ float g_fenh[BN * Dd];
__device__ float g_h   [BN * Dd];
__device__ float g_comp[BN * Mm];

// ============================================================
// SGEMM: C[M,N] = A[M,K] * B[N,K]^T + bias[N] (+ residual)
// Tile 128x128, 256 threads, 8x8 micro-tile via fma.rn.f32x2,
// K-chunk 16, double-buffered smem.
// ============================================================
__global__ __launch_bounds__(256) void sgemm_tn(
    const float* __restrict__ A, const float* __restrict__ B,
    const float* __restrict__ bias, const float* __restrict__ residual,
    float* __restrict__ C, int K, int N)
{
    __shared__ float As[2][16][132];
    __shared__ float Bs[2][16][132];
    const int tid = threadIdx.x;
    const int ty = tid >> 4, tx = tid & 15;
    const int rowBase = blockIdx.y * 128;
    const int colBase = blockIdx.x * 128;

    const int lr  = tid >> 2;          // 0..63 (x2 iters -> 0..127)
    const int lkq = (tid & 3) << 2;    // 0,4,8,12

    u64 acc[8][4];
    #pragma unroll
    for (int i = 0; i < 8; i++)
        #pragma unroll
        for (int j = 0; j < 4; j++) acc[i][j] = 0ull;

    float4 av[2], bv[2];
    // prefetch chunk 0
    #pragma unroll
    for (int it = 0; it < 2; it++) {
        int r = lr + it * 64;
        av[it] = *reinterpret_cast<const float4*>(A + (size_t)(rowBase + r) * K + lkq);
        bv[it] = *reinterpret_cast<const float4*>(B + (size_t)(colBase + r) * K + lkq);
    }
    // store chunk 0
    #pragma unroll
    for (int it = 0; it < 2; it++) {
        int r = lr + it * 64;
        As[0][lkq+0][r]=av[it].x; As[0][lkq+1][r]=av[it].y;
        As[0][lkq+2][r]=av[it].z; As[0][lkq+3][r]=av[it].w;
        Bs[0][lkq+0][r]=bv[it].x; Bs[0][lkq+1][r]=bv[it].y;
        Bs[0][lkq+2][r]=bv[it].z; Bs[0][lkq+3][r]=bv[it].w;
    }
    __syncthreads();

    int buf = 0;
    const int nChunk = K >> 4;
    for (int c = 1; c <= nChunk; c++) {
        if (c < nChunk) {
            int k0 = c << 4;
            #pragma unroll
            for (int it = 0; it < 2; it++) {
                int r = lr + it * 64;
                av[it] = *reinterpret_cast<const float4*>(A + (size_t)(rowBase + r) * K + k0 + lkq);
                bv[it] = *reinterpret_cast<const float4*>(B + (size_t)(colBase + r) * K + k0 + lkq);
            }
        }
        // compute on buf
        #pragma unroll
        for (int kk = 0; kk < 16; kk++) {
            float4 a0 = *reinterpret_cast<const float4*>(&As[buf][kk][ty * 8]);
            float4 a1 = *reinterpret_cast<const float4*>(&As[buf][kk][ty * 8 + 4]);
            float4 b0 = *reinterpret_cast<const float4*>(&Bs[buf][kk][tx * 8]);
            float4 b1 = *reinterpret_cast<const float4*>(&Bs[buf][kk][tx * 8 + 4]);
            u64 bb[4];
            bb[0] = pack2(b0.x, b0.y); bb[1] = pack2(b0.z, b0.w);
            bb[2] = pack2(b1.x, b1.y); bb[3] = pack2(b1.z, b1.w);
            float a[8] = {a0.x,a0.y,a0.z,a0.w,a1.x,a1.y,a1.z,a1.w};
            #pragma unroll
            for (int i = 0; i < 8; i++) {
                u64 ai = splat2(a[i]);
                #pragma unroll
                for (int j = 0; j < 4; j++) fma2(acc[i][j], ai, bb[j]);
            }
        }
        if (c < nChunk) {
            int nb = buf ^ 1;
            #pragma unroll
            for (int it = 0; it < 2; it++) {
                int r = lr + it * 64;
                As[nb][lkq+0][r]=av[it].x; As[nb][lkq+1][r]=av[it].y;
                As[nb][lkq+2][r]=av[it].z; As[nb][lkq+3][r]=av[it].w;
                Bs[nb][lkq+0][r]=bv[it].x; Bs[nb][lkq+1][r]=bv[it].y;
                Bs[nb][lkq+2][r]=bv[it].z; Bs[nb][lkq+3][r]=bv[it].w;
            }
            __syncthreads();
            buf = nb;
        }
    }

    #pragma unroll
    for (int i = 0; i < 8; i++) {
        int r = rowBase + ty * 8 + i;
        float4 o0, o1;
        float2 p0 = unpack2(acc[i][0]), p1 = unpack2(acc[i][1]);
        float2 p2 = unpack2(acc[i][2]), p3 = unpack2(acc[i][3]);
        o0.x=p0.x; o0.y=p0.y; o0.z=p1.x; o0.w=p1.y;
        o1.x=p2.x; o1.y=p2.y; o1.z=p3.x; o1.w=p3.y;
        int c = colBase + tx * 8;
        if (bias) {
            float4 bi0 = *reinterpret_cast<const float4*>(bias + c);
            float4 bi1 = *reinterpret_cast<const float4*>(bias + c + 4);
            o0.x+=bi0.x; o0.y+=bi0.y; o0.z+=bi0.z; o0.w+=bi0.w;
            o1.x+=bi1.x; o1.y+=bi1.y; o1.z+=bi1.z; o1.w+=bi1.w;
        }
        if (residual) {
            float4 r0 = *reinterpret_cast<const float4*>(residual + (size_t)r * N + c);
            float4 r1 = *reinterpret_cast<const float4*>(residual + (size_t)r * N + c + 4);
            o0.x+=r0.x; o0.y+=r0.y; o0.z+=r0.z; o0.w+=r0.w;
            o1.x+=r1.x; o1.y+=r1.y; o1.z+=r1.z; o1.w+=r1.w;
        }
        *reinterpret_cast<float4*>(C + (size_t)r * N + c)     = o0;
        *reinterpret_cast<float4*>(C + (size_t)r * N + c + 4) = o1;
    }
}

// ============================================================
// Fused flash attention, packed f32x2 micro-GEMMs.
// Per block: (b,h), 64-query tile, 32-key chunks.
// 256 threads: ty=tid>>4 (4 q-rows each), tx=tid&15.
// S tile per thread: 4x2 (cols 2tx+{0,1}); PV tile: 4x4.
// ============================================================
__global__ __launch_bounds__(256) void attn_kernel(
    const float* __restrict__ qkv, float* __restrict__ out)
{
    __shared__ float Qt[64][68];   // [dh][qrow]
    __shared__ float Kt[64][34];   // [dh][token]
    __shared__ float Vs[32][68];   // [token][dh]
    __shared__ float Pt[32][68];   // [token][qrow]

    const int tid = threadIdx.x;
    const int ty = tid >> 4, tx = tid & 15;
    const int bh = blockIdx.y;
    const int b = bh >> 3, h = bh & 7;
    const int q0 = blockIdx.x * 64;
    const float scale = 0.125f;

    // load Q tile transposed (scaled)
    const float* qbase = qkv + (size_t)(b * Nn + q0) * 1536 + h * 64;
    #pragma unroll
    for (int it = 0; it < 4; it++) {
        int f = tid + it * 256;
        int r = f >> 4;                  // 0..63 qrow
        int c = (f & 15) << 2;           // dh
        float4 v = *reinterpret_cast<const float4*>(qbase + (size_t)r * 1536 + c);
        Qt[c+0][r] = v.x * scale; Qt[c+1][r] = v.y * scale;
        Qt[c+2][r] = v.z * scale; Qt[c+3][r] = v.w * scale;
    }

    float m_i[4], l_i[4];
    u64 acc[4][2];
    #pragma unroll
    for (int i = 0; i < 4; i++) {
        m_i[i] = -1e30f; l_i[i] = 0.f;
        acc[i][0] = 0ull; acc[i][1] = 0ull;
    }

    const float* kbase = qkv + (size_t)(b * Nn) * 1536 + 512  + h * 64;
    const float* vbase = qkv + (size_t)(b * Nn) * 1536 + 1024 + h * 64;

    for (int kc = 0; kc < Nn; kc += 32) {
        __syncthreads();   // previous chunk's Kt/Vs/Pt fully consumed
        // load K chunk transposed + V chunk natural
        #pragma unroll
        for (int it = 0; it < 2; it++) {
            int f = tid + it * 256;
            int r = f >> 4;              // token 0..31
            int c = (f & 15) << 2;       // dh
            float4 kv = *reinterpret_cast<const float4*>(kbase + (size_t)(kc + r) * 1536 + c);
            Kt[c+0][r]=kv.x; Kt[c+1][r]=kv.y; Kt[c+2][r]=kv.z; Kt[c+3][r]=kv.w;
            float4 vv = *reinterpret_cast<const float4*>(vbase + (size_t)(kc + r) * 1536 + c);
            *reinterpret_cast<float4*>(&Vs[r][c]) = vv;
        }
        __syncthreads();

        // S = Q K^T : per thread rows 4ty+i, cols 2tx+{0,1}
        u64 s2[4] = {0ull, 0ull, 0ull, 0ull};
        #pragma unroll
        for (int kk = 0; kk < 64; kk++) {
            float4 a = *reinterpret_cast<const float4*>(&Qt[kk][4 * ty]);
            u64 bpair = *reinterpret_cast<const u64*>(&Kt[kk][2 * tx]);
            fma2(s2[0], splat2(a.x), bpair);
            fma2(s2[1], splat2(a.y), bpair);
            fma2(s2[2], splat2(a.z), bpair);
            fma2(s2[3], splat2(a.w), bpair);
        }

        // online softmax per row (reduce across 16 tx lanes)
        #pragma unroll
        for (int i = 0; i < 4; i++) {
            float2 sv = unpack2(s2[i]);
            float mx = fmaxf(sv.x, sv.y);
            #pragma unroll
            for (int o = 8; o >= 1; o >>= 1)
                mx = fmaxf(mx, __shfl_xor_sync(0xffffffffu, mx, o));
            float mnew = fmaxf(m_i[i], mx);
            float corr = __expf(m_i[i] - mnew);
            float p0 = __expf(sv.x - mnew);
            float p1 = __expf(sv.y - mnew);
            float ps = p0 + p1;
            #pragma unroll
            for (int o = 8; o >= 1; o >>= 1)
                ps += __shfl_xor_sync(0xffffffffu, ps, o);
            l_i[i] = l_i[i] * corr + ps;
            m_i[i] = mnew;
            u64 cs = splat2(corr);
            acc[i][0] = mul2(acc[i][0], cs);
            acc[i][1] = mul2(acc[i][1], cs);
            Pt[2 * tx][4 * ty + i]     = p0;
            Pt[2 * tx + 1][4 * ty + i] = p1;
        }
        __syncthreads();

        // acc += P^T-gather * V : per thread rows 4ty+i, cols 4tx+j
        #pragma unroll
        for (int kk = 0; kk < 32; kk++) {
            float4 a = *reinterpret_cast<const float4*>(&Pt[kk][4 * ty]);
            float4 v = *reinterpret_cast<const float4*>(&Vs[kk][4 * tx]);
            u64 v0 = pack2(v.x, v.y), v1 = pack2(v.z, v.w);
            fma2(acc[0][0], splat2(a.x), v0); fma2(acc[0][1], splat2(a.x), v1);
            fma2(acc[1][0], splat2(a.y), v0); fma2(acc[1][1], splat2(a.y), v1);
            fma2(acc[2][0], splat2(a.z), v0); fma2(acc[2][1], splat2(a.z), v1);
            fma2(acc[3][0], splat2(a.w), v0); fma2(acc[3][1], splat2(a.w), v1);
        }
    }

    float* obase = out + (size_t)(b * Nn + q0) * Dd + h * 64;
    #pragma unroll
    for (int i = 0; i < 4; i++) {
        float inv = 1.f / l_i[i];
        float2 p0 = unpack2(acc[i][0]), p1 = unpack2(acc[i][1]);
        float4 o; o.x = p0.x*inv; o.y = p0.y*inv; o.z = p1.x*inv; o.w = p1.y*inv;
        *reinterpret_cast<float4*>(obase + (size_t)(4 * ty + i) * Dd + 4 * tx) = o;
    }
}

// ============================================================
// Fused LayerNorm -> exact GELU -> components = h @ w2^T + b2
// ============================================================
__global__ __launch_bounds__(256) void ln_gelu_comp_kernel(
    const float* __restrict__ h,
    const float* __restrict__ ln_g, const float* __restrict__ ln_b,
    const float* __restrict__ w2,  const float* __restrict__ b2,
    float* __restrict__ comp)
{
    __shared__ float s[512];
    __shared__ float rs[8], rq[8];
    __shared__ float ps[16][17];

    const int row = blockIdx.x, tid = threadIdx.x;
    float x0 = h[(size_t)row * 512 + tid];
    float x1 = h[(size_t)row * 512 + 256 + tid];
    s[tid] = x0; s[tid + 256] = x1;
    float sum = x0 + x1, sq = x0 * x0 + x1 * x1;
    #pragma unroll
    for (int o = 16; o >= 1; o >>= 1) {
        sum += __shfl_xor_sync(0xffffffffu, sum, o);
        sq  += __shfl_xor_sync(0xffffffffu, sq,  o);
    }
    if ((tid & 31) == 0) { rs[tid >> 5] = sum; rq[tid >> 5] = sq; }
    __syncthreads();
    if (tid == 0) {
        float S = 0.f, Q = 0.f;
        #pragma unroll
        for (int i = 0; i < 8; i++) { S += rs[i]; Q += rq[i]; }
        rs[0] = S * (1.f / 512.f);
        rq[0] = Q * (1.f / 512.f);
    }
    __syncthreads();
    const float mean = rs[0];
    const float var  = rq[0] - mean * mean;
    const float rstd = rsqrtf(var + 1e-5f);

    #pragma unroll
    for (int e = tid; e < 512; e += 256) {
        float x = (s[e] - mean) * rstd * ln_g[e] + ln_b[e];
        s[e] = 0.5f * x * (1.f + erff(x * 0.70710678118f));
    }
    __syncthreads();

    const int m = tid & 15, ch = tid >> 4;
    float p = 0.f;
    const float* wrow = w2 + m * 512 + ch * 32;
    const float* srow = &s[ch * 32];
    #pragma unroll
    for (int e = 0; e < 32; e++) p += srow[e] * wrow[e];
    ps[ch][m] = p;
    __syncthreads();
    if (tid < 16) {
        float v = b2[tid];
        #pragma unroll
        for (int c = 0; c < 16; c++) v += ps[c][tid];
        comp[(size_t)row * 16 + tid] = v;
    }
}

// ============================================================
// Outer product + top-51 sparsify + coalesced [D,M] write.
// ============================================================
__global__ __launch_bounds__(512) void outer_topk_kernel(
    const float* __restrict__ F, const float* __restrict__ templates,
    const float* __restrict__ comp, float* __restrict__ out)
{
    __shared__ float Frow[512];
    __shared__ float cs[16];
    __shared__ float Qout[512 * 17];

    const int row = blockIdx.x;
    const int tid = threadIdx.x;
    const int m = tid >> 5, lid = tid & 31;

    Frow[tid] = F[(size_t)row * 512 + tid];
    if (tid < 16) cs[tid] = comp[(size_t)row * 16 + tid];
    __syncthreads();

    const float c = cs[m];
    float    qv[16];
    unsigned key[16];
    #pragma unroll
    for (int i = 0; i < 16; i++) {
        int d = lid + 32 * i;
        float q = Frow[d] * templates[m * 512 + d] * c;
        qv[i]  = q;
        key[i] = __float_as_uint(fabsf(q));
    }

    unsigned prefix = 0;
    for (int bit = 30; bit >= 0; bit--) {
        unsigned test = prefix | (1u << bit);
        int cnt = 0;
        #pragma unroll
        for (int i = 0; i < 16; i++) cnt += (key[i] >= test);
        cnt = __reduce_add_sync(0xffffffffu, cnt);
        if (cnt >= KTOP) prefix = test;
    }

    #pragma unroll
    for (int i = 0; i < 16; i++) {
        int d = lid + 32 * i;
        Qout[d * 17 + m] = (key[i] >= prefix) ? qv[i] : 0.f;
    }
    __syncthreads();

    float* ob = out + (size_t)row * (512 * 16);
    #pragma unroll
    for (int i = 0; i < 16; i++) {
        int e = tid + 512 * i;
        ob[e] = Qout[(e >> 4) * 17 + (e & 15)];
    }
}

// ============================================================
extern "C" void kernel_launch(void* const* d_in, const int* in_sizes, int n_in,
                              void* d_out, int out_size) {
    const float* F    = (const float*)d_in[0];
    const float* Wqkv = (const float*)d_in[1];
    const float* bqkv = (const float*)d_in[2];
    const float* Wout = (const float*)d_in[3];
    const float* bout = (const float*)d_in[4];
    const float* w1   = (const float*)d_in[5];
    const float* b1   = (const float*)d_in[6];
    const float* lng  = (const float*)d_in[7];
    const float* lnb  = (const float*)d_in[8];
    const float* w2   = (const float*)d_in[9];
    const float* b2   = (const float*)d_in[10];
    const float* tmpl = (const float*)d_in[11];
    float* out = (float*)d_out;

    float *qkv, *attn, *fenh, *hbuf, *comp;
    cudaGetSymbolAddress((void**)&qkv,  g_qkv);
    cudaGetSymbolAddress((void**)&attn, g_attn);
    cudaGetSymbolAddress((void**)&fenh, g_fenh);
    cudaGetSymbolAddress((void**)&hbuf, g_h);
    cudaGetSymbolAddress((void**)&comp, g_comp);

    sgemm_tn<<<dim3(1536 / 128, BN / 128), 256>>>(F, Wqkv, bqkv, nullptr, qkv, 512, 1536);
    attn_kernel<<<dim3(Nn / 64, Bb * Hh), 256>>>(qkv, attn);
    sgemm_tn<<<dim3(512 / 128, BN / 128), 256>>>(attn, Wout, bout, F, fenh, 512, 512);
    sgemm_tn<<<dim3(512 / 128, BN / 128), 256>>>(fenh, w1, b1, nullptr, hbuf, 512, 512);
    ln_gelu_comp_kernel<<<BN, 256>>>(hbuf, lng, lnb, w2, b2, comp);
    outer_topk_kernel<<<BN, 512>>>(F, tmpl, comp, out);
}

// round 4
// speedup vs baseline: 1.4735x; 1.3111x over previous
#include <cuda_runtime.h>
#include <cuda_bf16.h>
#include <math.h>

#define Bb   8
#define Nn   576
#define Dd   512
#define Mm   16
#define Hh   8
#define BN   (Bb*Nn)      // 4608
#define KTOP 51

typedef unsigned long long u64;
typedef unsigned int u32;

__device__ __forceinline__ u32 smem_u32(const void* p) {
    u32 a; asm("{ .reg .u64 t; cvta.to.shared.u64 t, %1; cvt.u32.u64 %0, t; }"
               : "=r"(a) : "l"(p));
    return a;
}

// ---- packed fp32x2 helpers (attention) ----
__device__ __forceinline__ u64 pack2(float lo, float hi) {
    u64 r; asm("mov.b64 %0, {%1, %2};" : "=l"(r) : "f"(lo), "f"(hi)); return r;
}
__device__ __forceinline__ u64 splat2(float x) {
    u64 r; asm("mov.b64 %0, {%1, %1};" : "=l"(r) : "f"(x)); return r;
}
__device__ __forceinline__ void fma2(u64& d, u64 a, u64 b) {
    asm("fma.rn.f32x2 %0, %1, %2, %3;" : "=l"(d) : "l"(a), "l"(b), "l"(d));
}
__device__ __forceinline__ u64 mul2(u64 a, u64 b) {
    u64 d; asm("mul.rn.f32x2 %0, %1, %2;" : "=l"(d) : "l"(a), "l"(b)); return d;
}
__device__ __forceinline__ float2 unpack2(u64 v) {
    float2 f; asm("mov.b64 {%0, %1}, %2;" : "=f"(f.x), "=f"(f.y) : "l"(v)); return f;
}

// ---- mma.sync helpers ----
__device__ __forceinline__ void ldsm4(u32& r0, u32& r1, u32& r2, u32& r3, u32 addr) {
    asm volatile("ldmatrix.sync.aligned.m8n8.x4.shared.b16 {%0,%1,%2,%3}, [%4];"
                 : "=r"(r0), "=r"(r1), "=r"(r2), "=r"(r3) : "r"(addr));
}
__device__ __forceinline__ void mma16816(float* c, const u32* a, const u32* b) {
    asm volatile(
        "mma.sync.aligned.m16n8k16.row.col.f32.bf16.bf16.f32 "
        "{%0,%1,%2,%3}, {%4,%5,%6,%7}, {%8,%9}, {%0,%1,%2,%3};"
        : "+f"(c[0]), "+f"(c[1]), "+f"(c[2]), "+f"(c[3])
        : "r"(a[0]), "r"(a[1]), "r"(a[2]), "r"(a[3]), "r"(b[0]), "r"(b[1]));
}
__device__ __forceinline__ void cvt_split(float4 v, u32& hi0, u32& hi1, u32& lo0, u32& lo1) {
    __nv_bfloat162 h0 = __float22bfloat162_rn(make_float2(v.x, v.y));
    __nv_bfloat162 h1 = __float22bfloat162_rn(make_float2(v.z, v.w));
    float2 f0 = __bfloat1622float2(h0), f1 = __bfloat1622float2(h1);
    __nv_bfloat162 l0 = __float22bfloat162_rn(make_float2(v.x - f0.x, v.y - f0.y));
    __nv_bfloat162 l1 = __float22bfloat162_rn(make_float2(v.z - f1.x, v.w - f1.y));
    hi0 = *(u32*)&h0; hi1 = *(u32*)&h1; lo0 = *(u32*)&l0; lo1 = *(u32*)&l1;
}

// ---- scratch ----
__device__ float g_qkv [BN * 3 * Dd];
__device__ float g_attn[BN * Dd];
__device__ float g_fenh[BN * Dd];
__device__ float g_h   [BN * Dd];
__device__ float g_comp[BN * Mm];

// ============================================================
// Tensor-core SGEMM via mma.sync: C[M,N] = A[M,K]*B[N,K]^T + bias (+res)
// bf16 hi/lo 3-term, fp32 acc. 128x128 tile, 8 warps (2x4), K-chunk 32,
// double-buffered smem, 144B row stride (aligned + conflict-free).
// ============================================================
#define ROWB 144                    // bytes per smem row (32 bf16 + pad)
#define ARR  (128 * ROWB)           // 18432 B per array
#define A_HI 0
#define A_LO (1 * ARR)
#define B_HI (2 * ARR)
#define B_LO (3 * ARR)
#define BUFSTR (4 * ARR)            // 73728
#define GEMM_SMEM (2 * BUFSTR)      // 147456

__global__ __launch_bounds__(256, 1) void sgemm_tc(
    const float* __restrict__ A, const float* __restrict__ B,
    const float* __restrict__ bias, const float* __restrict__ residual,
    float* __restrict__ C, int K, int N)
{
    extern __shared__ unsigned char smem[];
    const u32 sb = smem_u32(smem);

    const int tid = threadIdx.x;
    const int wid = tid >> 5, lid = tid & 31;
    const int rowBase = blockIdx.y * 128;
    const int colBase = blockIdx.x * 128;
    const int warp_m = (wid >> 2) * 64;
    const int warp_n = (wid & 3) * 32;

    // loader mapping: slot = tid + it*256; row = slot>>3; f4 = slot&7; k0 = f4*4
    const int lrow = tid >> 3;          // +32 per it
    const int lk0  = (tid & 7) << 2;    // element index in chunk
    const u32 stoff = (u32)lrow * ROWB + (u32)lk0 * 2;

    // ldmatrix lane bases
    const int a_row = warp_m + (lid & 15);
    const u32 a_kb  = (u32)(lid >> 4) * 16;            // bytes
    const int b_n   = warp_n + (lid & 7) + ((lid >> 4) << 3);
    const u32 b_kb  = (u32)((lid >> 3) & 1) * 16;      // bytes

    float acc[4][4][4];
    #pragma unroll
    for (int i = 0; i < 4; i++)
        #pragma unroll
        for (int j = 0; j < 4; j++)
            #pragma unroll
            for (int q = 0; q < 4; q++) acc[i][j][q] = 0.f;

    const int nChunk = K >> 5;   // 16 for K=512
    float4 av[4], bv[4];

    // prologue: load + store chunk 0
    #pragma unroll
    for (int it = 0; it < 4; it++) {
        int r = lrow + it * 32;
        av[it] = *reinterpret_cast<const float4*>(A + (size_t)(rowBase + r) * K + lk0);
        bv[it] = *reinterpret_cast<const float4*>(B + (size_t)(colBase + r) * K + lk0);
    }
    #pragma unroll
    for (int it = 0; it < 4; it++) {
        u32 o = stoff + (u32)it * (32u * ROWB);
        u32 h0, h1, l0, l1;
        cvt_split(av[it], h0, h1, l0, l1);
        *reinterpret_cast<uint2*>(smem + A_HI + o) = make_uint2(h0, h1);
        *reinterpret_cast<uint2*>(smem + A_LO + o) = make_uint2(l0, l1);
        cvt_split(bv[it], h0, h1, l0, l1);
        *reinterpret_cast<uint2*>(smem + B_HI + o) = make_uint2(h0, h1);
        *reinterpret_cast<uint2*>(smem + B_LO + o) = make_uint2(l0, l1);
    }
    __syncthreads();

    for (int c = 0; c < nChunk; c++) {
        if (c + 1 < nChunk) {
            int k0 = (c + 1) << 5;
            #pragma unroll
            for (int it = 0; it < 4; it++) {
                int r = lrow + it * 32;
                av[it] = *reinterpret_cast<const float4*>(A + (size_t)(rowBase + r) * K + k0 + lk0);
                bv[it] = *reinterpret_cast<const float4*>(B + (size_t)(colBase + r) * K + k0 + lk0);
            }
        }

        // ---- compute chunk c from buffer c&1 ----
        const u32 bufo = (u32)(c & 1) * BUFSTR;
        #pragma unroll
        for (int ks = 0; ks < 2; ks++) {
            const u32 kso = (u32)ks * 32;   // 16 bf16 = 32 bytes
            u32 bhi[2][4], blo[2][4];
            #pragma unroll
            for (int np = 0; np < 2; np++) {
                u32 ba = sb + bufo + (u32)(b_n + np * 16) * ROWB + kso + b_kb;
                ldsm4(bhi[np][0], bhi[np][1], bhi[np][2], bhi[np][3], ba + B_HI);
                ldsm4(blo[np][0], blo[np][1], blo[np][2], blo[np][3], ba + B_LO);
            }
            #pragma unroll
            for (int mt = 0; mt < 4; mt++) {
                u32 aa = sb + bufo + (u32)(a_row + mt * 16) * ROWB + kso + a_kb;
                u32 ahi[4], alo[4];
                ldsm4(ahi[0], ahi[1], ahi[2], ahi[3], aa + A_HI);
                ldsm4(alo[0], alo[1], alo[2], alo[3], aa + A_LO);
                #pragma unroll
                for (int nt = 0; nt < 4; nt++) {
                    const u32* bh = &bhi[nt >> 1][(nt & 1) * 2];
                    const u32* bl = &blo[nt >> 1][(nt & 1) * 2];
                    mma16816(acc[mt][nt], ahi, bh);
                    mma16816(acc[mt][nt], ahi, bl);
                    mma16816(acc[mt][nt], alo, bh);
                }
            }
        }

        if (c + 1 < nChunk) {
            const u32 nb = (u32)((c + 1) & 1) * BUFSTR;
            #pragma unroll
            for (int it = 0; it < 4; it++) {
                u32 o = nb + stoff + (u32)it * (32u * ROWB);
                u32 h0, h1, l0, l1;
                cvt_split(av[it], h0, h1, l0, l1);
                *reinterpret_cast<uint2*>(smem + A_HI + o) = make_uint2(h0, h1);
                *reinterpret_cast<uint2*>(smem + A_LO + o) = make_uint2(l0, l1);
                cvt_split(bv[it], h0, h1, l0, l1);
                *reinterpret_cast<uint2*>(smem + B_HI + o) = make_uint2(h0, h1);
                *reinterpret_cast<uint2*>(smem + B_LO + o) = make_uint2(l0, l1);
            }
            __syncthreads();
        }
    }

    // ---- epilogue: write fragments directly ----
    const int frow = lid >> 2;            // 0..7
    const int fcol = (lid & 3) * 2;
    #pragma unroll
    for (int mt = 0; mt < 4; mt++) {
        #pragma unroll
        for (int nt = 0; nt < 4; nt++) {
            int col = colBase + warp_n + nt * 8 + fcol;
            float2 bi = *reinterpret_cast<const float2*>(bias + col);
            #pragma unroll
            for (int half = 0; half < 2; half++) {
                int r = rowBase + warp_m + mt * 16 + frow + half * 8;
                float2 o;
                o.x = acc[mt][nt][half * 2 + 0] + bi.x;
                o.y = acc[mt][nt][half * 2 + 1] + bi.y;
                if (residual) {
                    float2 rv = *reinterpret_cast<const float2*>(residual + (size_t)r * N + col);
                    o.x += rv.x; o.y += rv.y;
                }
                *reinterpret_cast<float2*>(C + (size_t)r * N + col) = o;
            }
        }
    }
}

// ============================================================
// Fused flash attention (packed f32x2) — unchanged (R2 passing)
// ============================================================
__global__ __launch_bounds__(256) void attn_kernel(
    const float* __restrict__ qkv, float* __restrict__ out)
{
    __shared__ float Qt[64][68];
    __shared__ float Kt[64][34];
    __shared__ float Vs[32][68];
    __shared__ float Pt[32][68];

    const int tid = threadIdx.x;
    const int ty = tid >> 4, tx = tid & 15;
    const int bh = blockIdx.y;
    const int b = bh >> 3, h = bh & 7;
    const int q0 = blockIdx.x * 64;
    const float scale = 0.125f;

    const float* qbase = qkv + (size_t)(b * Nn + q0) * 1536 + h * 64;
    #pragma unroll
    for (int it = 0; it < 4; it++) {
        int f = tid + it * 256;
        int r = f >> 4;
        int c = (f & 15) << 2;
        float4 v = *reinterpret_cast<const float4*>(qbase + (size_t)r * 1536 + c);
        Qt[c+0][r] = v.x * scale; Qt[c+1][r] = v.y * scale;
        Qt[c+2][r] = v.z * scale; Qt[c+3][r] = v.w * scale;
    }

    float m_i[4], l_i[4];
    u64 acc[4][2];
    #pragma unroll
    for (int i = 0; i < 4; i++) {
        m_i[i] = -1e30f; l_i[i] = 0.f;
        acc[i][0] = 0ull; acc[i][1] = 0ull;
    }

    const float* kbase = qkv + (size_t)(b * Nn) * 1536 + 512  + h * 64;
    const float* vbase = qkv + (size_t)(b * Nn) * 1536 + 1024 + h * 64;

    for (int kc = 0; kc < Nn; kc += 32) {
        __syncthreads();
        #pragma unroll
        for (int it = 0; it < 2; it++) {
            int f = tid + it * 256;
            int r = f >> 4;
            int c = (f & 15) << 2;
            float4 kv = *reinterpret_cast<const float4*>(kbase + (size_t)(kc + r) * 1536 + c);
            Kt[c+0][r]=kv.x; Kt[c+1][r]=kv.y; Kt[c+2][r]=kv.z; Kt[c+3][r]=kv.w;
            float4 vv = *reinterpret_cast<const float4*>(vbase + (size_t)(kc + r) * 1536 + c);
            *reinterpret_cast<float4*>(&Vs[r][c]) = vv;
        }
        __syncthreads();

        u64 s2[4] = {0ull, 0ull, 0ull, 0ull};
        #pragma unroll
        for (int kk = 0; kk < 64; kk++) {
            float4 a = *reinterpret_cast<const float4*>(&Qt[kk][4 * ty]);
            u64 bpair = *reinterpret_cast<const u64*>(&Kt[kk][2 * tx]);
            fma2(s2[0], splat2(a.x), bpair);
            fma2(s2[1], splat2(a.y), bpair);
            fma2(s2[2], splat2(a.z), bpair);
            fma2(s2[3], splat2(a.w), bpair);
        }

        #pragma unroll
        for (int i = 0; i < 4; i++) {
            float2 sv = unpack2(s2[i]);
            float mx = fmaxf(sv.x, sv.y);
            #pragma unroll
            for (int o = 8; o >= 1; o >>= 1)
                mx = fmaxf(mx, __shfl_xor_sync(0xffffffffu, mx, o));
            float mnew = fmaxf(m_i[i], mx);
            float corr = __expf(m_i[i] - mnew);
            float p0 = __expf(sv.x - mnew);
            float p1 = __expf(sv.y - mnew);
            float ps = p0 + p1;
            #pragma unroll
            for (int o = 8; o >= 1; o >>= 1)
                ps += __shfl_xor_sync(0xffffffffu, ps, o);
            l_i[i] = l_i[i] * corr + ps;
            m_i[i] = mnew;
            u64 cs = splat2(corr);
            acc[i][0] = mul2(acc[i][0], cs);
            acc[i][1] = mul2(acc[i][1], cs);
            Pt[2 * tx][4 * ty + i]     = p0;
            Pt[2 * tx + 1][4 * ty + i] = p1;
        }
        __syncthreads();

        #pragma unroll
        for (int kk = 0; kk < 32; kk++) {
            float4 a = *reinterpret_cast<const float4*>(&Pt[kk][4 * ty]);
            float4 v = *reinterpret_cast<const float4*>(&Vs[kk][4 * tx]);
            u64 v0 = pack2(v.x, v.y), v1 = pack2(v.z, v.w);
            fma2(acc[0][0], splat2(a.x), v0); fma2(acc[0][1], splat2(a.x), v1);
            fma2(acc[1][0], splat2(a.y), v0); fma2(acc[1][1], splat2(a.y), v1);
            fma2(acc[2][0], splat2(a.z), v0); fma2(acc[2][1], splat2(a.z), v1);
            fma2(acc[3][0], splat2(a.w), v0); fma2(acc[3][1], splat2(a.w), v1);
        }
    }

    float* obase = out + (size_t)(b * Nn + q0) * Dd + h * 64;
    #pragma unroll
    for (int i = 0; i < 4; i++) {
        float inv = 1.f / l_i[i];
        float2 p0 = unpack2(acc[i][0]), p1 = unpack2(acc[i][1]);
        float4 o; o.x = p0.x*inv; o.y = p0.y*inv; o.z = p1.x*inv; o.w = p1.y*inv;
        *reinterpret_cast<float4*>(obase + (size_t)(4 * ty + i) * Dd + 4 * tx) = o;
    }
}

// ============================================================
// Fused LayerNorm -> exact GELU -> components = h @ w2^T + b2
// ============================================================
__global__ __launch_bounds__(256) void ln_gelu_comp_kernel(
    const float* __restrict__ h,
    const float* __restrict__ ln_g, const float* __restrict__ ln_b,
    const float* __restrict__ w2,  const float* __restrict__ b2,
    float* __restrict__ comp)
{
    __shared__ float s[512];
    __shared__ float rs[8], rq[8];
    __shared__ float ps[16][17];

    const int row = blockIdx.x, tid = threadIdx.x;
    float x0 = h[(size_t)row * 512 + tid];
    float x1 = h[(size_t)row * 512 + 256 + tid];
    s[tid] = x0; s[tid + 256] = x1;
    float sum = x0 + x1, sq = x0 * x0 + x1 * x1;
    #pragma unroll
    for (int o = 16; o >= 1; o >>= 1) {
        sum += __shfl_xor_sync(0xffffffffu, sum, o);
        sq  += __shfl_xor_sync(0xffffffffu, sq,  o);
    }
    if ((tid & 31) == 0) { rs[tid >> 5] = sum; rq[tid >> 5] = sq; }
    __syncthreads();
    if (tid == 0) {
        float S = 0.f, Q = 0.f;
        #pragma unroll
        for (int i = 0; i < 8; i++) { S += rs[i]; Q += rq[i]; }
        rs[0] = S * (1.f / 512.f);
        rq[0] = Q * (1.f / 512.f);
    }
    __syncthreads();
    const float mean = rs[0];
    const float var  = rq[0] - mean * mean;
    const float rstd = rsqrtf(var + 1e-5f);

    #pragma unroll
    for (int e = tid; e < 512; e += 256) {
        float x = (s[e] - mean) * rstd * ln_g[e] + ln_b[e];
        s[e] = 0.5f * x * (1.f + erff(x * 0.70710678118f));
    }
    __syncthreads();

    const int m = tid & 15, ch = tid >> 4;
    float p = 0.f;
    const float* wrow = w2 + m * 512 + ch * 32;
    const float* srow = &s[ch * 32];
    #pragma unroll
    for (int e = 0; e < 32; e++) p += srow[e] * wrow[e];
    ps[ch][m] = p;
    __syncthreads();
    if (tid < 16) {
        float v = b2[tid];
        #pragma unroll
        for (int c = 0; c < 16; c++) v += ps[c][tid];
        comp[(size_t)row * 16 + tid] = v;
    }
}

// ============================================================
// Outer product + top-51 sparsify + coalesced [D,M] write.
// ============================================================
__global__ __launch_bounds__(512) void outer_topk_kernel(
    const float* __restrict__ F, const float* __restrict__ templates,
    const float* __restrict__ comp, float* __restrict__ out)
{
    __shared__ float Frow[512];
    __shared__ float cs[16];
    __shared__ float Qout[512 * 17];

    const int row = blockIdx.x;
    const int tid = threadIdx.x;
    const int m = tid >> 5, lid = tid & 31;

    Frow[tid] = F[(size_t)row * 512 + tid];
    if (tid < 16) cs[tid] = comp[(size_t)row * 16 + tid];
    __syncthreads();

    const float c = cs[m];
    float    qv[16];
    unsigned key[16];
    #pragma unroll
    for (int i = 0; i < 16; i++) {
        int d = lid + 32 * i;
        float q = Frow[d] * templates[m * 512 + d] * c;
        qv[i]  = q;
        key[i] = __float_as_uint(fabsf(q));
    }

    unsigned prefix = 0;
    for (int bit = 30; bit >= 0; bit--) {
        unsigned test = prefix | (1u << bit);
        int cnt = 0;
        #pragma unroll
        for (int i = 0; i < 16; i++) cnt += (key[i] >= test);
        cnt = __reduce_add_sync(0xffffffffu, cnt);
        if (cnt >= KTOP) prefix = test;
    }

    #pragma unroll
    for (int i = 0; i < 16; i++) {
        int d = lid + 32 * i;
        Qout[d * 17 + m] = (key[i] >= prefix) ? qv[i] : 0.f;
    }
    __syncthreads();

    float* ob = out + (size_t)row * (512 * 16);
    #pragma unroll
    for (int i = 0; i < 16; i++) {
        int e = tid + 512 * i;
        ob[e] = Qout[(e >> 4) * 17 + (e & 15)];
    }
}

// ============================================================
extern "C" void kernel_launch(void* const* d_in, const int* in_sizes, int n_in,
                              void* d_out, int out_size) {
    const float* F    = (const float*)d_in[0];
    const float* Wqkv = (const float*)d_in[1];
    const float* bqkv = (const float*)d_in[2];
    const float* Wout = (const float*)d_in[3];
    const float* bout = (const float*)d_in[4];
    const float* w1   = (const float*)d_in[5];
    const float* b1   = (const float*)d_in[6];
    const float* lng  = (const float*)d_in[7];
    const float* lnb  = (const float*)d_in[8];
    const float* w2   = (const float*)d_in[9];
    const float* b2   = (const float*)d_in[10];
    const float* tmpl = (const float*)d_in[11];
    float* out = (float*)d_out;

    float *qkv, *attn, *fenh, *hbuf, *comp;
    cudaGetSymbolAddress((void**)&qkv,  g_qkv);
    cudaGetSymbolAddress((void**)&attn, g_attn);
    cudaGetSymbolAddress((void**)&fenh, g_fenh);
    cudaGetSymbolAddress((void**)&hbuf, g_h);
    cudaGetSymbolAddress((void**)&comp, g_comp);

    cudaFuncSetAttribute(sgemm_tc, cudaFuncAttributeMaxDynamicSharedMemorySize,
                         GEMM_SMEM);

    sgemm_tc<<<dim3(1536 / 128, BN / 128), 256, GEMM_SMEM>>>(
        F, Wqkv, bqkv, nullptr, qkv, 512, 1536);
    attn_kernel<<<dim3(Nn / 64, Bb * Hh), 256>>>(qkv, attn);
    sgemm_tc<<<dim3(512 / 128, BN / 128), 256, GEMM_SMEM>>>(
        attn, Wout, bout, F, fenh, 512, 512);
    sgemm_tc<<<dim3(512 / 128, BN / 128), 256, GEMM_SMEM>>>(
        fenh, w1, b1, nullptr, hbuf, 512, 512);
    ln_gelu_comp_kernel<<<BN, 256>>>(hbuf, lng, lnb, w2, b2, comp);
    outer_topk_kernel<<<BN, 512>>>(F, tmpl, comp, out);
}

// round 5
// speedup vs baseline: 1.7592x; 1.1939x over previous
#include <cuda_runtime.h>
#include <cuda_bf16.h>
#include <math.h>

#define Bb   8
#define Nn   576
#define Dd   512
#define Mm   16
#define Hh   8
#define BN   (Bb*Nn)      // 4608
#define KTOP 51

typedef unsigned long long u64;
typedef unsigned int u32;

__device__ __forceinline__ u32 smem_u32(const void* p) {
    u32 a; asm("{ .reg .u64 t; cvta.to.shared.u64 t, %1; cvt.u32.u64 %0, t; }"
               : "=r"(a) : "l"(p));
    return a;
}

// ---- mma.sync helpers ----
__device__ __forceinline__ void ldsm4(u32* r, u32 addr) {
    asm volatile("ldmatrix.sync.aligned.m8n8.x4.shared.b16 {%0,%1,%2,%3}, [%4];"
                 : "=r"(r[0]), "=r"(r[1]), "=r"(r[2]), "=r"(r[3]) : "r"(addr));
}
__device__ __forceinline__ void ldsm4t(u32* r, u32 addr) {
    asm volatile("ldmatrix.sync.aligned.m8n8.x4.trans.shared.b16 {%0,%1,%2,%3}, [%4];"
                 : "=r"(r[0]), "=r"(r[1]), "=r"(r[2]), "=r"(r[3]) : "r"(addr));
}
__device__ __forceinline__ void mma16816(float* c, const u32* a, const u32* b) {
    asm volatile(
        "mma.sync.aligned.m16n8k16.row.col.f32.bf16.bf16.f32 "
        "{%0,%1,%2,%3}, {%4,%5,%6,%7}, {%8,%9}, {%0,%1,%2,%3};"
        : "+f"(c[0]), "+f"(c[1]), "+f"(c[2]), "+f"(c[3])
        : "r"(a[0]), "r"(a[1]), "r"(a[2]), "r"(a[3]), "r"(b[0]), "r"(b[1]));
}
__device__ __forceinline__ void cvt_split(float4 v, u32& hi0, u32& hi1, u32& lo0, u32& lo1) {
    __nv_bfloat162 h0 = __float22bfloat162_rn(make_float2(v.x, v.y));
    __nv_bfloat162 h1 = __float22bfloat162_rn(make_float2(v.z, v.w));
    float2 f0 = __bfloat1622float2(h0), f1 = __bfloat1622float2(h1);
    __nv_bfloat162 l0 = __float22bfloat162_rn(make_float2(v.x - f0.x, v.y - f0.y));
    __nv_bfloat162 l1 = __float22bfloat162_rn(make_float2(v.z - f1.x, v.w - f1.y));
    hi0 = *(u32*)&h0; hi1 = *(u32*)&h1; lo0 = *(u32*)&l0; lo1 = *(u32*)&l1;
}
__device__ __forceinline__ void cvt_split2(float x, float y, u32& hi, u32& lo) {
    __nv_bfloat162 h = __float22bfloat162_rn(make_float2(x, y));
    float2 f = __bfloat1622float2(h);
    __nv_bfloat162 l = __float22bfloat162_rn(make_float2(x - f.x, y - f.y));
    hi = *(u32*)&h; lo = *(u32*)&l;
}

// ---- scratch ----
__device__ float g_qkv [BN * 3 * Dd];
__device__ float g_attn[BN * Dd];
__device__ float g_fenh[BN * Dd];
__device__ float g_h   [BN * Dd];
__device__ float g_comp[BN * Mm];

// ============================================================
// Tensor-core SGEMM (unchanged, R4-passing)
// ============================================================
#define ROWB 144
#define ARR  (128 * ROWB)
#define A_HI 0
#define A_LO (1 * ARR)
#define B_HI (2 * ARR)
#define B_LO (3 * ARR)
#define BUFSTR (4 * ARR)
#define GEMM_SMEM (2 * BUFSTR)

__global__ __launch_bounds__(256, 1) void sgemm_tc(
    const float* __restrict__ A, const float* __restrict__ B,
    const float* __restrict__ bias, const float* __restrict__ residual,
    float* __restrict__ C, int K, int N)
{
    extern __shared__ unsigned char smem[];
    const u32 sb = smem_u32(smem);

    const int tid = threadIdx.x;
    const int wid = tid >> 5, lid = tid & 31;
    const int rowBase = blockIdx.y * 128;
    const int colBase = blockIdx.x * 128;
    const int warp_m = (wid >> 2) * 64;
    const int warp_n = (wid & 3) * 32;

    const int lrow = tid >> 3;
    const int lk0  = (tid & 7) << 2;
    const u32 stoff = (u32)lrow * ROWB + (u32)lk0 * 2;

    const int a_row = warp_m + (lid & 15);
    const u32 a_kb  = (u32)(lid >> 4) * 16;
    const int b_n   = warp_n + (lid & 7) + ((lid >> 4) << 3);
    const u32 b_kb  = (u32)((lid >> 3) & 1) * 16;

    float acc[4][4][4];
    #pragma unroll
    for (int i = 0; i < 4; i++)
        #pragma unroll
        for (int j = 0; j < 4; j++)
            #pragma unroll
            for (int q = 0; q < 4; q++) acc[i][j][q] = 0.f;

    const int nChunk = K >> 5;
    float4 av[4], bv[4];

    #pragma unroll
    for (int it = 0; it < 4; it++) {
        int r = lrow + it * 32;
        av[it] = *reinterpret_cast<const float4*>(A + (size_t)(rowBase + r) * K + lk0);
        bv[it] = *reinterpret_cast<const float4*>(B + (size_t)(colBase + r) * K + lk0);
    }
    #pragma unroll
    for (int it = 0; it < 4; it++) {
        u32 o = stoff + (u32)it * (32u * ROWB);
        u32 h0, h1, l0, l1;
        cvt_split(av[it], h0, h1, l0, l1);
        *reinterpret_cast<uint2*>(smem + A_HI + o) = make_uint2(h0, h1);
        *reinterpret_cast<uint2*>(smem + A_LO + o) = make_uint2(l0, l1);
        cvt_split(bv[it], h0, h1, l0, l1);
        *reinterpret_cast<uint2*>(smem + B_HI + o) = make_uint2(h0, h1);
        *reinterpret_cast<uint2*>(smem + B_LO + o) = make_uint2(l0, l1);
    }
    __syncthreads();

    for (int c = 0; c < nChunk; c++) {
        if (c + 1 < nChunk) {
            int k0 = (c + 1) << 5;
            #pragma unroll
            for (int it = 0; it < 4; it++) {
                int r = lrow + it * 32;
                av[it] = *reinterpret_cast<const float4*>(A + (size_t)(rowBase + r) * K + k0 + lk0);
                bv[it] = *reinterpret_cast<const float4*>(B + (size_t)(colBase + r) * K + k0 + lk0);
            }
        }

        const u32 bufo = (u32)(c & 1) * BUFSTR;
        #pragma unroll
        for (int ks = 0; ks < 2; ks++) {
            const u32 kso = (u32)ks * 32;
            u32 bhi[2][4], blo[2][4];
            #pragma unroll
            for (int np = 0; np < 2; np++) {
                u32 ba = sb + bufo + (u32)(b_n + np * 16) * ROWB + kso + b_kb;
                ldsm4(bhi[np], ba + B_HI);
                ldsm4(blo[np], ba + B_LO);
            }
            #pragma unroll
            for (int mt = 0; mt < 4; mt++) {
                u32 aa = sb + bufo + (u32)(a_row + mt * 16) * ROWB + kso + a_kb;
                u32 ahi[4], alo[4];
                ldsm4(ahi, aa + A_HI);
                ldsm4(alo, aa + A_LO);
                #pragma unroll
                for (int nt = 0; nt < 4; nt++) {
                    const u32* bh = &bhi[nt >> 1][(nt & 1) * 2];
                    const u32* bl = &blo[nt >> 1][(nt & 1) * 2];
                    mma16816(acc[mt][nt], ahi, bh);
                    mma16816(acc[mt][nt], ahi, bl);
                    mma16816(acc[mt][nt], alo, bh);
                }
            }
        }

        if (c + 1 < nChunk) {
            const u32 nb = (u32)((c + 1) & 1) * BUFSTR;
            #pragma unroll
            for (int it = 0; it < 4; it++) {
                u32 o = nb + stoff + (u32)it * (32u * ROWB);
                u32 h0, h1, l0, l1;
                cvt_split(av[it], h0, h1, l0, l1);
                *reinterpret_cast<uint2*>(smem + A_HI + o) = make_uint2(h0, h1);
                *reinterpret_cast<uint2*>(smem + A_LO + o) = make_uint2(l0, l1);
                cvt_split(bv[it], h0, h1, l0, l1);
                *reinterpret_cast<uint2*>(smem + B_HI + o) = make_uint2(h0, h1);
                *reinterpret_cast<uint2*>(smem + B_LO + o) = make_uint2(l0, l1);
            }
            __syncthreads();
        }
    }

    const int frow = lid >> 2;
    const int fcol = (lid & 3) * 2;
    #pragma unroll
    for (int mt = 0; mt < 4; mt++) {
        #pragma unroll
        for (int nt = 0; nt < 4; nt++) {
            int col = colBase + warp_n + nt * 8 + fcol;
            float2 bi = *reinterpret_cast<const float2*>(bias + col);
            #pragma unroll
            for (int half = 0; half < 2; half++) {
                int r = rowBase + warp_m + mt * 16 + frow + half * 8;
                float2 o;
                o.x = acc[mt][nt][half * 2 + 0] + bi.x;
                o.y = acc[mt][nt][half * 2 + 1] + bi.y;
                if (residual) {
                    float2 rv = *reinterpret_cast<const float2*>(residual + (size_t)r * N + col);
                    o.x += rv.x; o.y += rv.y;
                }
                *reinterpret_cast<float2*>(C + (size_t)r * N + col) = o;
            }
        }
    }
}

// ============================================================
// Tensor-core flash attention. Block = (b,h) x 64-q tile,
// 128 threads (4 warps x 16 q-rows). 64-key chunks.
// bf16 hi/lo 3-term for S=QK^T and O+=PV. Fragment softmax.
// smem rows: 72 bf16 = 144B (aligned + conflict-free).
// ============================================================
#define AT_QHI 0
#define AT_QLO 9216
#define AT_KHI 18432
#define AT_KLO 27648
#define AT_VHI 36864
#define AT_VLO 46080
#define ATTN_SMEM 55296

__global__ __launch_bounds__(128) void attn_tc(
    const float* __restrict__ qkv, float* __restrict__ out)
{
    extern __shared__ unsigned char smem[];
    const u32 sb = smem_u32(smem);

    const int tid = threadIdx.x;
    const int wid = tid >> 5, lid = tid & 31;
    const int bh = blockIdx.y;
    const int b = bh >> 3, h = bh & 7;
    const int q0 = blockIdx.x * 64;

    // ---- load Q tile (scaled by 1/8), hi/lo split ----
    const float* qbase = qkv + (size_t)(b * Nn + q0) * 1536 + h * 64;
    #pragma unroll
    for (int it = 0; it < 8; it++) {
        int slot = tid + it * 128;
        int row = slot >> 4;
        int c4 = (slot & 15) << 2;
        float4 v = *reinterpret_cast<const float4*>(qbase + (size_t)row * 1536 + c4);
        v.x *= 0.125f; v.y *= 0.125f; v.z *= 0.125f; v.w *= 0.125f;
        u32 h0, h1, l0, l1;
        cvt_split(v, h0, h1, l0, l1);
        u32 o = (u32)row * ROWB + (u32)c4 * 2;
        *reinterpret_cast<uint2*>(smem + AT_QHI + o) = make_uint2(h0, h1);
        *reinterpret_cast<uint2*>(smem + AT_QLO + o) = make_uint2(l0, l1);
    }
    __syncthreads();

    // ---- hoist Q fragments (constant across key chunks) ----
    u32 qh[4][4], ql[4][4];
    {
        const int a_row = (wid << 4) + (lid & 15);
        const u32 a_kb = (u32)(lid >> 4) * 16;
        #pragma unroll
        for (int kt = 0; kt < 4; kt++) {
            u32 addr = sb + AT_QHI + (u32)a_row * ROWB + (u32)kt * 32 + a_kb;
            ldsm4(qh[kt], addr);
            ldsm4(ql[kt], addr + (AT_QLO - AT_QHI));
        }
    }

    float m_lo = -1e30f, m_hi = -1e30f, l_lo = 0.f, l_hi = 0.f;
    float oacc[8][4];
    #pragma unroll
    for (int j = 0; j < 8; j++)
        #pragma unroll
        for (int q = 0; q < 4; q++) oacc[j][q] = 0.f;

    const float* kbase = qkv + (size_t)(b * Nn) * 1536 + 512  + h * 64;
    const float* vbase = qkv + (size_t)(b * Nn) * 1536 + 1024 + h * 64;

    // fragment address components
    const int kb_row = (lid & 7) + ((lid >> 4) << 3);   // K ldmatrix row-in-group
    const u32 kb_kb  = (u32)((lid >> 3) & 1) * 16;
    const int vb_key = (lid & 7) + (((lid >> 3) & 1) << 3);  // V trans: key row
    const u32 vb_db  = (u32)(lid >> 4) * 16;                  // V trans: dh byte off

    for (int kc = 0; kc < Nn; kc += 64) {
        __syncthreads();
        // ---- load K,V chunk (64 keys x 64 dh), hi/lo split ----
        #pragma unroll
        for (int it = 0; it < 8; it++) {
            int slot = tid + it * 128;
            int row = slot >> 4;
            int c4 = (slot & 15) << 2;
            u32 o = (u32)row * ROWB + (u32)c4 * 2;
            float4 kv = *reinterpret_cast<const float4*>(kbase + (size_t)(kc + row) * 1536 + c4);
            u32 h0, h1, l0, l1;
            cvt_split(kv, h0, h1, l0, l1);
            *reinterpret_cast<uint2*>(smem + AT_KHI + o) = make_uint2(h0, h1);
            *reinterpret_cast<uint2*>(smem + AT_KLO + o) = make_uint2(l0, l1);
            float4 vv = *reinterpret_cast<const float4*>(vbase + (size_t)(kc + row) * 1536 + c4);
            cvt_split(vv, h0, h1, l0, l1);
            *reinterpret_cast<uint2*>(smem + AT_VHI + o) = make_uint2(h0, h1);
            *reinterpret_cast<uint2*>(smem + AT_VLO + o) = make_uint2(l0, l1);
        }
        __syncthreads();

        // ---- S = Q K^T : 8 n-tiles (64 keys), 4 k-steps (dh 64) ----
        float sacc[8][4];
        #pragma unroll
        for (int j = 0; j < 8; j++)
            #pragma unroll
            for (int q = 0; q < 4; q++) sacc[j][q] = 0.f;

        #pragma unroll
        for (int kt = 0; kt < 4; kt++) {
            #pragma unroll
            for (int ng = 0; ng < 4; ng++) {
                u32 ka = sb + AT_KHI + (u32)(ng * 16 + kb_row) * ROWB + (u32)kt * 32 + kb_kb;
                u32 kh[4], kl[4];
                ldsm4(kh, ka);
                ldsm4(kl, ka + (AT_KLO - AT_KHI));
                #pragma unroll
                for (int half = 0; half < 2; half++) {
                    float* s = sacc[2 * ng + half];
                    const u32* bh = &kh[half * 2];
                    const u32* bl = &kl[half * 2];
                    mma16816(s, qh[kt], bh);
                    mma16816(s, qh[kt], bl);
                    mma16816(s, ql[kt], bh);
                }
            }
        }

        // ---- fragment online softmax ----
        float mx_lo = -1e30f, mx_hi = -1e30f;
        #pragma unroll
        for (int j = 0; j < 8; j++) {
            mx_lo = fmaxf(mx_lo, fmaxf(sacc[j][0], sacc[j][1]));
            mx_hi = fmaxf(mx_hi, fmaxf(sacc[j][2], sacc[j][3]));
        }
        #pragma unroll
        for (int o = 1; o <= 2; o <<= 1) {
            mx_lo = fmaxf(mx_lo, __shfl_xor_sync(0xffffffffu, mx_lo, o));
            mx_hi = fmaxf(mx_hi, __shfl_xor_sync(0xffffffffu, mx_hi, o));
        }
        float mn_lo = fmaxf(m_lo, mx_lo), mn_hi = fmaxf(m_hi, mx_hi);
        float corr_lo = __expf(m_lo - mn_lo), corr_hi = __expf(m_hi - mn_hi);
        float rs_lo = 0.f, rs_hi = 0.f;
        #pragma unroll
        for (int j = 0; j < 8; j++) {
            sacc[j][0] = __expf(sacc[j][0] - mn_lo);
            sacc[j][1] = __expf(sacc[j][1] - mn_lo);
            sacc[j][2] = __expf(sacc[j][2] - mn_hi);
            sacc[j][3] = __expf(sacc[j][3] - mn_hi);
            rs_lo += sacc[j][0] + sacc[j][1];
            rs_hi += sacc[j][2] + sacc[j][3];
        }
        #pragma unroll
        for (int o = 1; o <= 2; o <<= 1) {
            rs_lo += __shfl_xor_sync(0xffffffffu, rs_lo, o);
            rs_hi += __shfl_xor_sync(0xffffffffu, rs_hi, o);
        }
        l_lo = l_lo * corr_lo + rs_lo;
        l_hi = l_hi * corr_hi + rs_hi;
        m_lo = mn_lo; m_hi = mn_hi;
        #pragma unroll
        for (int j = 0; j < 8; j++) {
            oacc[j][0] *= corr_lo; oacc[j][1] *= corr_lo;
            oacc[j][2] *= corr_hi; oacc[j][3] *= corr_hi;
        }

        // ---- O += P V : k = keys (4 ksteps), n = dh (8 n-tiles) ----
        #pragma unroll
        for (int kt = 0; kt < 4; kt++) {
            const int j0 = 2 * kt, j1 = 2 * kt + 1;
            u32 aph[4], apl[4];
            cvt_split2(sacc[j0][0], sacc[j0][1], aph[0], apl[0]);
            cvt_split2(sacc[j0][2], sacc[j0][3], aph[1], apl[1]);
            cvt_split2(sacc[j1][0], sacc[j1][1], aph[2], apl[2]);
            cvt_split2(sacc[j1][2], sacc[j1][3], aph[3], apl[3]);
            #pragma unroll
            for (int ng = 0; ng < 4; ng++) {
                u32 va = sb + AT_VHI + (u32)(kt * 16 + vb_key) * ROWB + (u32)ng * 32 + vb_db;
                u32 vh[4], vl[4];
                ldsm4t(vh, va);
                ldsm4t(vl, va + (AT_VLO - AT_VHI));
                #pragma unroll
                for (int half = 0; half < 2; half++) {
                    float* oa = oacc[2 * ng + half];
                    const u32* bh = &vh[half * 2];
                    const u32* bl = &vl[half * 2];
                    mma16816(oa, aph, bh);
                    mma16816(oa, aph, bl);
                    mma16816(oa, apl, bh);
                }
            }
        }
    }

    // ---- write O / l ----
    const float inv_lo = 1.f / l_lo, inv_hi = 1.f / l_hi;
    const int r_lo = q0 + (wid << 4) + (lid >> 2);
    const int cb = h * 64 + (lid & 3) * 2;
    #pragma unroll
    for (int j = 0; j < 8; j++) {
        int col = cb + j * 8;
        float2 w0, w1;
        w0.x = oacc[j][0] * inv_lo; w0.y = oacc[j][1] * inv_lo;
        w1.x = oacc[j][2] * inv_hi; w1.y = oacc[j][3] * inv_hi;
        *reinterpret_cast<float2*>(out + (size_t)(b * Nn + r_lo) * Dd + col)     = w0;
        *reinterpret_cast<float2*>(out + (size_t)(b * Nn + r_lo + 8) * Dd + col) = w1;
    }
}

// ============================================================
// Fused LayerNorm -> exact GELU -> components = h @ w2^T + b2
// ============================================================
__global__ __launch_bounds__(256) void ln_gelu_comp_kernel(
    const float* __restrict__ h,
    const float* __restrict__ ln_g, const float* __restrict__ ln_b,
    const float* __restrict__ w2,  const float* __restrict__ b2,
    float* __restrict__ comp)
{
    __shared__ float s[512];
    __shared__ float rs[8], rq[8];
    __shared__ float ps[16][17];

    const int row = blockIdx.x, tid = threadIdx.x;
    float x0 = h[(size_t)row * 512 + tid];
    float x1 = h[(size_t)row * 512 + 256 + tid];
    s[tid] = x0; s[tid + 256] = x1;
    float sum = x0 + x1, sq = x0 * x0 + x1 * x1;
    #pragma unroll
    for (int o = 16; o >= 1; o >>= 1) {
        sum += __shfl_xor_sync(0xffffffffu, sum, o);
        sq  += __shfl_xor_sync(0xffffffffu, sq,  o);
    }
    if ((tid & 31) == 0) { rs[tid >> 5] = sum; rq[tid >> 5] = sq; }
    __syncthreads();
    if (tid == 0) {
        float S = 0.f, Q = 0.f;
        #pragma unroll
        for (int i = 0; i < 8; i++) { S += rs[i]; Q += rq[i]; }
        rs[0] = S * (1.f / 512.f);
        rq[0] = Q * (1.f / 512.f);
    }
    __syncthreads();
    const float mean = rs[0];
    const float var  = rq[0] - mean * mean;
    const float rstd = rsqrtf(var + 1e-5f);

    #pragma unroll
    for (int e = tid; e < 512; e += 256) {
        float x = (s[e] - mean) * rstd * ln_g[e] + ln_b[e];
        s[e] = 0.5f * x * (1.f + erff(x * 0.70710678118f));
    }
    __syncthreads();

    const int m = tid & 15, ch = tid >> 4;
    float p = 0.f;
    const float* wrow = w2 + m * 512 + ch * 32;
    const float* srow = &s[ch * 32];
    #pragma unroll
    for (int e = 0; e < 32; e++) p += srow[e] * wrow[e];
    ps[ch][m] = p;
    __syncthreads();
    if (tid < 16) {
        float v = b2[tid];
        #pragma unroll
        for (int c = 0; c < 16; c++) v += ps[c][tid];
        comp[(size_t)row * 16 + tid] = v;
    }
}

// ============================================================
// Outer product + top-51 sparsify + coalesced [D,M] write.
// ============================================================
__global__ __launch_bounds__(512) void outer_topk_kernel(
    const float* __restrict__ F, const float* __restrict__ templates,
    const float* __restrict__ comp, float* __restrict__ out)
{
    __shared__ float Frow[512];
    __shared__ float cs[16];
    __shared__ float Qout[512 * 17];

    const int row = blockIdx.x;
    const int tid = threadIdx.x;
    const int m = tid >> 5, lid = tid & 31;

    Frow[tid] = F[(size_t)row * 512 + tid];
    if (tid < 16) cs[tid] = comp[(size_t)row * 16 + tid];
    __syncthreads();

    const float c = cs[m];
    float    qv[16];
    unsigned key[16];
    #pragma unroll
    for (int i = 0; i < 16; i++) {
        int d = lid + 32 * i;
        float q = Frow[d] * templates[m * 512 + d] * c;
        qv[i]  = q;
        key[i] = __float_as_uint(fabsf(q));
    }

    unsigned prefix = 0;
    for (int bit = 30; bit >= 0; bit--) {
        unsigned test = prefix | (1u << bit);
        int cnt = 0;
        #pragma unroll
        for (int i = 0; i < 16; i++) cnt += (key[i] >= test);
        cnt = __reduce_add_sync(0xffffffffu, cnt);
        if (cnt >= KTOP) prefix = test;
    }

    #pragma unroll
    for (int i = 0; i < 16; i++) {
        int d = lid + 32 * i;
        Qout[d * 17 + m] = (key[i] >= prefix) ? qv[i] : 0.f;
    }
    __syncthreads();

    float* ob = out + (size_t)row * (512 * 16);
    #pragma unroll
    for (int i = 0; i < 16; i++) {
        int e = tid + 512 * i;
        ob[e] = Qout[(e >> 4) * 17 + (e & 15)];
    }
}

// ============================================================
extern "C" void kernel_launch(void* const* d_in, const int* in_sizes, int n_in,
                              void* d_out, int out_size) {
    const float* F    = (const float*)d_in[0];
    const float* Wqkv = (const float*)d_in[1];
    const float* bqkv = (const float*)d_in[2];
    const float* Wout = (const float*)d_in[3];
    const float* bout = (const float*)d_in[4];
    const float* w1   = (const float*)d_in[5];
    const float* b1   = (const float*)d_in[6];
    const float* lng  = (const float*)d_in[7];
    const float* lnb  = (const float*)d_in[8];
    const float* w2   = (const float*)d_in[9];
    const float* b2   = (const float*)d_in[10];
    const float* tmpl = (const float*)d_in[11];
    float* out = (float*)d_out;

    float *qkv, *attn, *fenh, *hbuf, *comp;
    cudaGetSymbolAddress((void**)&qkv,  g_qkv);
    cudaGetSymbolAddress((void**)&attn, g_attn);
    cudaGetSymbolAddress((void**)&fenh, g_fenh);
    cudaGetSymbolAddress((void**)&hbuf, g_h);
    cudaGetSymbolAddress((void**)&comp, g_comp);

    cudaFuncSetAttribute(sgemm_tc, cudaFuncAttributeMaxDynamicSharedMemorySize,
                         GEMM_SMEM);
    cudaFuncSetAttribute(attn_tc, cudaFuncAttributeMaxDynamicSharedMemorySize,
                         ATTN_SMEM);

    sgemm_tc<<<dim3(1536 / 128, BN / 128), 256, GEMM_SMEM>>>(
        F, Wqkv, bqkv, nullptr, qkv, 512, 1536);
    attn_tc<<<dim3(Nn / 64, Bb * Hh), 128, ATTN_SMEM>>>(qkv, attn);
    sgemm_tc<<<dim3(512 / 128, BN / 128), 256, GEMM_SMEM>>>(
        attn, Wout, bout, F, fenh, 512, 512);
    sgemm_tc<<<dim3(512 / 128, BN / 128), 256, GEMM_SMEM>>>(
        fenh, w1, b1, nullptr, hbuf, 512, 512);
    ln_gelu_comp_kernel<<<BN, 256>>>(hbuf, lng, lnb, w2, b2, comp);
    outer_topk_kernel<<<BN, 512>>>(F, tmpl, comp, out);
}

// round 6
// speedup vs baseline: 1.8330x; 1.0419x over previous
#include <cuda_runtime.h>
#include <cuda_bf16.h>
#include <math.h>

#define Bb   8
#define Nn   576
#define Dd   512
#define Mm   16
#define Hh   8
#define BN   (Bb*Nn)      // 4608
#define KTOP 51

typedef unsigned long long u64;
typedef unsigned int u32;

__device__ __forceinline__ u32 smem_u32(const void* p) {
    u32 a; asm("{ .reg .u64 t; cvta.to.shared.u64 t, %1; cvt.u32.u64 %0, t; }"
               : "=r"(a) : "l"(p));
    return a;
}

// ---- mma.sync helpers ----
__device__ __forceinline__ void ldsm4(u32* r, u32 addr) {
    asm volatile("ldmatrix.sync.aligned.m8n8.x4.shared.b16 {%0,%1,%2,%3}, [%4];"
                 : "=r"(r[0]), "=r"(r[1]), "=r"(r[2]), "=r"(r[3]) : "r"(addr));
}
__device__ __forceinline__ void ldsm4t(u32* r, u32 addr) {
    asm volatile("ldmatrix.sync.aligned.m8n8.x4.trans.shared.b16 {%0,%1,%2,%3}, [%4];"
                 : "=r"(r[0]), "=r"(r[1]), "=r"(r[2]), "=r"(r[3]) : "r"(addr));
}
__device__ __forceinline__ void mma16816(float* c, const u32* a, const u32* b) {
    asm volatile(
        "mma.sync.aligned.m16n8k16.row.col.f32.bf16.bf16.f32 "
        "{%0,%1,%2,%3}, {%4,%5,%6,%7}, {%8,%9}, {%0,%1,%2,%3};"
        : "+f"(c[0]), "+f"(c[1]), "+f"(c[2]), "+f"(c[3])
        : "r"(a[0]), "r"(a[1]), "r"(a[2]), "r"(a[3]), "r"(b[0]), "r"(b[1]));
}
__device__ __forceinline__ void cvt_split(float4 v, u32& hi0, u32& hi1, u32& lo0, u32& lo1) {
    __nv_bfloat162 h0 = __float22bfloat162_rn(make_float2(v.x, v.y));
    __nv_bfloat162 h1 = __float22bfloat162_rn(make_float2(v.z, v.w));
    float2 f0 = __bfloat1622float2(h0), f1 = __bfloat1622float2(h1);
    __nv_bfloat162 l0 = __float22bfloat162_rn(make_float2(v.x - f0.x, v.y - f0.y));
    __nv_bfloat162 l1 = __float22bfloat162_rn(make_float2(v.z - f1.x, v.w - f1.y));
    hi0 = *(u32*)&h0; hi1 = *(u32*)&h1; lo0 = *(u32*)&l0; lo1 = *(u32*)&l1;
}
__device__ __forceinline__ void cvt_split2(float x, float y, u32& hi, u32& lo) {
    __nv_bfloat162 h = __float22bfloat162_rn(make_float2(x, y));
    float2 f = __bfloat1622float2(h);
    __nv_bfloat162 l = __float22bfloat162_rn(make_float2(x - f.x, y - f.y));
    hi = *(u32*)&h; lo = *(u32*)&l;
}

// ---- scratch ----
__device__ __nv_bfloat16 g_qhi[BN * 3 * Dd];  // split qkv (Q pre-scaled 1/8)
__device__ __nv_bfloat16 g_qlo[BN * 3 * Dd];
__device__ float g_attn[BN * Dd];
__device__ float g_fenh[BN * Dd];
__device__ float g_h   [BN * Dd];
__device__ float g_comp[BN * Mm];

// ============================================================
// Tensor-core SGEMM: C = A*B^T + bias (+res). Optionally emits
// bf16 hi/lo split outputs (Q cols < 512 pre-scaled by 1/8).
// ============================================================
#define ROWB 144
#define ARR  (128 * ROWB)
#define A_HI 0
#define A_LO (1 * ARR)
#define B_HI (2 * ARR)
#define B_LO (3 * ARR)
#define BUFSTR (4 * ARR)
#define GEMM_SMEM (2 * BUFSTR)

__global__ __launch_bounds__(256, 1) void sgemm_tc(
    const float* __restrict__ A, const float* __restrict__ B,
    const float* __restrict__ bias, const float* __restrict__ residual,
    float* __restrict__ C,
    __nv_bfloat16* __restrict__ Shi, __nv_bfloat16* __restrict__ Slo,
    int qsplit, int K, int N)
{
    extern __shared__ unsigned char smem[];
    const u32 sb = smem_u32(smem);

    const int tid = threadIdx.x;
    const int wid = tid >> 5, lid = tid & 31;
    const int rowBase = blockIdx.y * 128;
    const int colBase = blockIdx.x * 128;
    const int warp_m = (wid >> 2) * 64;
    const int warp_n = (wid & 3) * 32;

    const int lrow = tid >> 3;
    const int lk0  = (tid & 7) << 2;
    const u32 stoff = (u32)lrow * ROWB + (u32)lk0 * 2;

    const int a_row = warp_m + (lid & 15);
    const u32 a_kb  = (u32)(lid >> 4) * 16;
    const int b_n   = warp_n + (lid & 7) + ((lid >> 4) << 3);
    const u32 b_kb  = (u32)((lid >> 3) & 1) * 16;

    float acc[4][4][4];
    #pragma unroll
    for (int i = 0; i < 4; i++)
        #pragma unroll
        for (int j = 0; j < 4; j++)
            #pragma unroll
            for (int q = 0; q < 4; q++) acc[i][j][q] = 0.f;

    const int nChunk = K >> 5;
    float4 av[4], bv[4];

    #pragma unroll
    for (int it = 0; it < 4; it++) {
        int r = lrow + it * 32;
        av[it] = *reinterpret_cast<const float4*>(A + (size_t)(rowBase + r) * K + lk0);
        bv[it] = *reinterpret_cast<const float4*>(B + (size_t)(colBase + r) * K + lk0);
    }
    #pragma unroll
    for (int it = 0; it < 4; it++) {
        u32 o = stoff + (u32)it * (32u * ROWB);
        u32 h0, h1, l0, l1;
        cvt_split(av[it], h0, h1, l0, l1);
        *reinterpret_cast<uint2*>(smem + A_HI + o) = make_uint2(h0, h1);
        *reinterpret_cast<uint2*>(smem + A_LO + o) = make_uint2(l0, l1);
        cvt_split(bv[it], h0, h1, l0, l1);
        *reinterpret_cast<uint2*>(smem + B_HI + o) = make_uint2(h0, h1);
        *reinterpret_cast<uint2*>(smem + B_LO + o) = make_uint2(l0, l1);
    }
    __syncthreads();

    for (int c = 0; c < nChunk; c++) {
        if (c + 1 < nChunk) {
            int k0 = (c + 1) << 5;
            #pragma unroll
            for (int it = 0; it < 4; it++) {
                int r = lrow + it * 32;
                av[it] = *reinterpret_cast<const float4*>(A + (size_t)(rowBase + r) * K + k0 + lk0);
                bv[it] = *reinterpret_cast<const float4*>(B + (size_t)(colBase + r) * K + k0 + lk0);
            }
        }

        const u32 bufo = (u32)(c & 1) * BUFSTR;
        #pragma unroll
        for (int ks = 0; ks < 2; ks++) {
            const u32 kso = (u32)ks * 32;
            u32 bhi[2][4], blo[2][4];
            #pragma unroll
            for (int np = 0; np < 2; np++) {
                u32 ba = sb + bufo + (u32)(b_n + np * 16) * ROWB + kso + b_kb;
                ldsm4(bhi[np], ba + B_HI);
                ldsm4(blo[np], ba + B_LO);
            }
            #pragma unroll
            for (int mt = 0; mt < 4; mt++) {
                u32 aa = sb + bufo + (u32)(a_row + mt * 16) * ROWB + kso + a_kb;
                u32 ahi[4], alo[4];
                ldsm4(ahi, aa + A_HI);
                ldsm4(alo, aa + A_LO);
                #pragma unroll
                for (int nt = 0; nt < 4; nt++) {
                    const u32* bh = &bhi[nt >> 1][(nt & 1) * 2];
                    const u32* bl = &blo[nt >> 1][(nt & 1) * 2];
                    mma16816(acc[mt][nt], ahi, bh);
                    mma16816(acc[mt][nt], ahi, bl);
                    mma16816(acc[mt][nt], alo, bh);
                }
            }
        }

        if (c + 1 < nChunk) {
            const u32 nb = (u32)((c + 1) & 1) * BUFSTR;
            #pragma unroll
            for (int it = 0; it < 4; it++) {
                u32 o = nb + stoff + (u32)it * (32u * ROWB);
                u32 h0, h1, l0, l1;
                cvt_split(av[it], h0, h1, l0, l1);
                *reinterpret_cast<uint2*>(smem + A_HI + o) = make_uint2(h0, h1);
                *reinterpret_cast<uint2*>(smem + A_LO + o) = make_uint2(l0, l1);
                cvt_split(bv[it], h0, h1, l0, l1);
                *reinterpret_cast<uint2*>(smem + B_HI + o) = make_uint2(h0, h1);
                *reinterpret_cast<uint2*>(smem + B_LO + o) = make_uint2(l0, l1);
            }
            __syncthreads();
        }
    }

    const int frow = lid >> 2;
    const int fcol = (lid & 3) * 2;
    #pragma unroll
    for (int mt = 0; mt < 4; mt++) {
        #pragma unroll
        for (int nt = 0; nt < 4; nt++) {
            int col = colBase + warp_n + nt * 8 + fcol;
            float2 bi = *reinterpret_cast<const float2*>(bias + col);
            #pragma unroll
            for (int half = 0; half < 2; half++) {
                int r = rowBase + warp_m + mt * 16 + frow + half * 8;
                float2 o;
                o.x = acc[mt][nt][half * 2 + 0] + bi.x;
                o.y = acc[mt][nt][half * 2 + 1] + bi.y;
                if (residual) {
                    float2 rv = *reinterpret_cast<const float2*>(residual + (size_t)r * N + col);
                    o.x += rv.x; o.y += rv.y;
                }
                if (C)
                    *reinterpret_cast<float2*>(C + (size_t)r * N + col) = o;
                if (Shi) {
                    float sc = (qsplit && col < 512) ? 0.125f : 1.0f;
                    u32 hb, lb;
                    cvt_split2(o.x * sc, o.y * sc, hb, lb);
                    *reinterpret_cast<u32*>(Shi + (size_t)r * N + col) = hb;
                    *reinterpret_cast<u32*>(Slo + (size_t)r * N + col) = lb;
                }
            }
        }
    }
}

// ============================================================
// Tensor-core flash attention, inputs pre-split bf16 hi/lo.
// Block = (b,h) x 64-q tile, 128 threads. Pure uint4 smem copies.
// ============================================================
#define AT_QHI 0
#define AT_QLO 9216
#define AT_KHI 18432
#define AT_KLO 27648
#define AT_VHI 36864
#define AT_VLO 46080
#define ATTN_SMEM 55296

__global__ __launch_bounds__(128) void attn_tc(
    const __nv_bfloat16* __restrict__ ghi, const __nv_bfloat16* __restrict__ glo,
    float* __restrict__ out)
{
    extern __shared__ unsigned char smem[];
    const u32 sb = smem_u32(smem);

    const int tid = threadIdx.x;
    const int wid = tid >> 5, lid = tid & 31;
    const int bh = blockIdx.y;
    const int b = bh >> 3, h = bh & 7;
    const int q0 = blockIdx.x * 64;

    const __nv_bfloat16* qhi = ghi + (size_t)(b * Nn + q0) * 1536 + h * 64;
    const __nv_bfloat16* qlo = glo + (size_t)(b * Nn + q0) * 1536 + h * 64;

    // ---- copy Q tile (already scaled+split) ----
    #pragma unroll
    for (int it = 0; it < 4; it++) {
        int s = tid + it * 128;
        int row = s >> 3;
        int c8 = s & 7;
        size_t go = (size_t)row * 1536 + c8 * 8;
        u32 o = (u32)row * ROWB + (u32)c8 * 16;
        *reinterpret_cast<uint4*>(smem + AT_QHI + o) = *reinterpret_cast<const uint4*>(qhi + go);
        *reinterpret_cast<uint4*>(smem + AT_QLO + o) = *reinterpret_cast<const uint4*>(qlo + go);
    }
    __syncthreads();

    // ---- hoist Q fragments ----
    u32 qh[4][4], ql[4][4];
    {
        const int a_row = (wid << 4) + (lid & 15);
        const u32 a_kb = (u32)(lid >> 4) * 16;
        #pragma unroll
        for (int kt = 0; kt < 4; kt++) {
            u32 addr = sb + AT_QHI + (u32)a_row * ROWB + (u32)kt * 32 + a_kb;
            ldsm4(qh[kt], addr);
            ldsm4(ql[kt], addr + (AT_QLO - AT_QHI));
        }
    }

    float m_lo = -1e30f, m_hi = -1e30f, l_lo = 0.f, l_hi = 0.f;
    float oacc[8][4];
    #pragma unroll
    for (int j = 0; j < 8; j++)
        #pragma unroll
        for (int q = 0; q < 4; q++) oacc[j][q] = 0.f;

    const __nv_bfloat16* khi = ghi + (size_t)(b * Nn) * 1536 + 512  + h * 64;
    const __nv_bfloat16* klo = glo + (size_t)(b * Nn) * 1536 + 512  + h * 64;
    const __nv_bfloat16* vhi = ghi + (size_t)(b * Nn) * 1536 + 1024 + h * 64;
    const __nv_bfloat16* vlo = glo + (size_t)(b * Nn) * 1536 + 1024 + h * 64;

    const int kb_row = (lid & 7) + ((lid >> 4) << 3);
    const u32 kb_kb  = (u32)((lid >> 3) & 1) * 16;
    const int vb_key = (lid & 7) + (((lid >> 3) & 1) << 3);
    const u32 vb_db  = (u32)(lid >> 4) * 16;

    for (int kc = 0; kc < Nn; kc += 64) {
        __syncthreads();
        // ---- copy K,V chunk (pre-split) ----
        #pragma unroll
        for (int it = 0; it < 4; it++) {
            int s = tid + it * 128;
            int row = s >> 3;
            int c8 = s & 7;
            size_t go = (size_t)(kc + row) * 1536 + c8 * 8;
            u32 o = (u32)row * ROWB + (u32)c8 * 16;
            *reinterpret_cast<uint4*>(smem + AT_KHI + o) = *reinterpret_cast<const uint4*>(khi + go);
            *reinterpret_cast<uint4*>(smem + AT_KLO + o) = *reinterpret_cast<const uint4*>(klo + go);
            *reinterpret_cast<uint4*>(smem + AT_VHI + o) = *reinterpret_cast<const uint4*>(vhi + go);
            *reinterpret_cast<uint4*>(smem + AT_VLO + o) = *reinterpret_cast<const uint4*>(vlo + go);
        }
        __syncthreads();

        // ---- S = Q K^T ----
        float sacc[8][4];
        #pragma unroll
        for (int j = 0; j < 8; j++)
            #pragma unroll
            for (int q = 0; q < 4; q++) sacc[j][q] = 0.f;

        #pragma unroll
        for (int kt = 0; kt < 4; kt++) {
            #pragma unroll
            for (int ng = 0; ng < 4; ng++) {
                u32 ka = sb + AT_KHI + (u32)(ng * 16 + kb_row) * ROWB + (u32)kt * 32 + kb_kb;
                u32 kh[4], kl[4];
                ldsm4(kh, ka);
                ldsm4(kl, ka + (AT_KLO - AT_KHI));
                #pragma unroll
                for (int half = 0; half < 2; half++) {
                    float* s = sacc[2 * ng + half];
                    const u32* bh = &kh[half * 2];
                    const u32* bl = &kl[half * 2];
                    mma16816(s, qh[kt], bh);
                    mma16816(s, qh[kt], bl);
                    mma16816(s, ql[kt], bh);
                }
            }
        }

        // ---- fragment online softmax ----
        float mx_lo = -1e30f, mx_hi = -1e30f;
        #pragma unroll
        for (int j = 0; j < 8; j++) {
            mx_lo = fmaxf(mx_lo, fmaxf(sacc[j][0], sacc[j][1]));
            mx_hi = fmaxf(mx_hi, fmaxf(sacc[j][2], sacc[j][3]));
        }
        #pragma unroll
        for (int o = 1; o <= 2; o <<= 1) {
            mx_lo = fmaxf(mx_lo, __shfl_xor_sync(0xffffffffu, mx_lo, o));
            mx_hi = fmaxf(mx_hi, __shfl_xor_sync(0xffffffffu, mx_hi, o));
        }
        float mn_lo = fmaxf(m_lo, mx_lo), mn_hi = fmaxf(m_hi, mx_hi);
        float corr_lo = __expf(m_lo - mn_lo), corr_hi = __expf(m_hi - mn_hi);
        float rs_lo = 0.f, rs_hi = 0.f;
        #pragma unroll
        for (int j = 0; j < 8; j++) {
            sacc[j][0] = __expf(sacc[j][0] - mn_lo);
            sacc[j][1] = __expf(sacc[j][1] - mn_lo);
            sacc[j][2] = __expf(sacc[j][2] - mn_hi);
            sacc[j][3] = __expf(sacc[j][3] - mn_hi);
            rs_lo += sacc[j][0] + sacc[j][1];
            rs_hi += sacc[j][2] + sacc[j][3];
        }
        #pragma unroll
        for (int o = 1; o <= 2; o <<= 1) {
            rs_lo += __shfl_xor_sync(0xffffffffu, rs_lo, o);
            rs_hi += __shfl_xor_sync(0xffffffffu, rs_hi, o);
        }
        l_lo = l_lo * corr_lo + rs_lo;
        l_hi = l_hi * corr_hi + rs_hi;
        m_lo = mn_lo; m_hi = mn_hi;
        #pragma unroll
        for (int j = 0; j < 8; j++) {
            oacc[j][0] *= corr_lo; oacc[j][1] *= corr_lo;
            oacc[j][2] *= corr_hi; oacc[j][3] *= corr_hi;
        }

        // ---- O += P V ----
        #pragma unroll
        for (int kt = 0; kt < 4; kt++) {
            const int j0 = 2 * kt, j1 = 2 * kt + 1;
            u32 aph[4], apl[4];
            cvt_split2(sacc[j0][0], sacc[j0][1], aph[0], apl[0]);
            cvt_split2(sacc[j0][2], sacc[j0][3], aph[1], apl[1]);
            cvt_split2(sacc[j1][0], sacc[j1][1], aph[2], apl[2]);
            cvt_split2(sacc[j1][2], sacc[j1][3], aph[3], apl[3]);
            #pragma unroll
            for (int ng = 0; ng < 4; ng++) {
                u32 va = sb + AT_VHI + (u32)(kt * 16 + vb_key) * ROWB + (u32)ng * 32 + vb_db;
                u32 vh[4], vl[4];
                ldsm4t(vh, va);
                ldsm4t(vl, va + (AT_VLO - AT_VHI));
                #pragma unroll
                for (int half = 0; half < 2; half++) {
                    float* oa = oacc[2 * ng + half];
                    const u32* bh = &vh[half * 2];
                    const u32* bl = &vl[half * 2];
                    mma16816(oa, aph, bh);
                    mma16816(oa, aph, bl);
                    mma16816(oa, apl, bh);
                }
            }
        }
    }

    // ---- write O ----
    const float inv_lo = 1.f / l_lo, inv_hi = 1.f / l_hi;
    const int r_lo = q0 + (wid << 4) + (lid >> 2);
    const int cb = h * 64 + (lid & 3) * 2;
    #pragma unroll
    for (int j = 0; j < 8; j++) {
        int col = cb + j * 8;
        float2 w0, w1;
        w0.x = oacc[j][0] * inv_lo; w0.y = oacc[j][1] * inv_lo;
        w1.x = oacc[j][2] * inv_hi; w1.y = oacc[j][3] * inv_hi;
        *reinterpret_cast<float2*>(out + (size_t)(b * Nn + r_lo) * Dd + col)     = w0;
        *reinterpret_cast<float2*>(out + (size_t)(b * Nn + r_lo + 8) * Dd + col) = w1;
    }
}

// ============================================================
// Fused LayerNorm -> exact GELU -> components = h @ w2^T + b2
// ============================================================
__global__ __launch_bounds__(256) void ln_gelu_comp_kernel(
    const float* __restrict__ h,
    const float* __restrict__ ln_g, const float* __restrict__ ln_b,
    const float* __restrict__ w2,  const float* __restrict__ b2,
    float* __restrict__ comp)
{
    __shared__ float s[512];
    __shared__ float rs[8], rq[8];
    __shared__ float ps[16][17];

    const int row = blockIdx.x, tid = threadIdx.x;
    float x0 = h[(size_t)row * 512 + tid];
    float x1 = h[(size_t)row * 512 + 256 + tid];
    s[tid] = x0; s[tid + 256] = x1;
    float sum = x0 + x1, sq = x0 * x0 + x1 * x1;
    #pragma unroll
    for (int o = 16; o >= 1; o >>= 1) {
        sum += __shfl_xor_sync(0xffffffffu, sum, o);
        sq  += __shfl_xor_sync(0xffffffffu, sq,  o);
    }
    if ((tid & 31) == 0) { rs[tid >> 5] = sum; rq[tid >> 5] = sq; }
    __syncthreads();
    if (tid == 0) {
        float S = 0.f, Q = 0.f;
        #pragma unroll
        for (int i = 0; i < 8; i++) { S += rs[i]; Q += rq[i]; }
        rs[0] = S * (1.f / 512.f);
        rq[0] = Q * (1.f / 512.f);
    }
    __syncthreads();
    const float mean = rs[0];
    const float var  = rq[0] - mean * mean;
    const float rstd = rsqrtf(var + 1e-5f);

    #pragma unroll
    for (int e = tid; e < 512; e += 256) {
        float x = (s[e] - mean) * rstd * ln_g[e] + ln_b[e];
        s[e] = 0.5f * x * (1.f + erff(x * 0.70710678118f));
    }
    __syncthreads();

    const int m = tid & 15, ch = tid >> 4;
    float p = 0.f;
    const float* wrow = w2 + m * 512 + ch * 32;
    const float* srow = &s[ch * 32];
    #pragma unroll
    for (int e = 0; e < 32; e++) p += srow[e] * wrow[e];
    ps[ch][m] = p;
    __syncthreads();
    if (tid < 16) {
        float v = b2[tid];
        #pragma unroll
        for (int c = 0; c < 16; c++) v += ps[c][tid];
        comp[(size_t)row * 16 + tid] = v;
    }
}

// ============================================================
// Outer product + top-51 sparsify + coalesced [D,M] write.
// ============================================================
__global__ __launch_bounds__(512) void outer_topk_kernel(
    const float* __restrict__ F, const float* __restrict__ templates,
    const float* __restrict__ comp, float* __restrict__ out)
{
    __shared__ float Frow[512];
    __shared__ float cs[16];
    __shared__ float Qout[512 * 17];

    const int row = blockIdx.x;
    const int tid = threadIdx.x;
    const int m = tid >> 5, lid = tid & 31;

    Frow[tid] = F[(size_t)row * 512 + tid];
    if (tid < 16) cs[tid] = comp[(size_t)row * 16 + tid];
    __syncthreads();

    const float c = cs[m];
    float    qv[16];
    unsigned key[16];
    #pragma unroll
    for (int i = 0; i < 16; i++) {
        int d = lid + 32 * i;
        float q = Frow[d] * templates[m * 512 + d] * c;
        qv[i]  = q;
        key[i] = __float_as_uint(fabsf(q));
    }

    unsigned prefix = 0;
    for (int bit = 30; bit >= 0; bit--) {
        unsigned test = prefix | (1u << bit);
        int cnt = 0;
        #pragma unroll
        for (int i = 0; i < 16; i++) cnt += (key[i] >= test);
        cnt = __reduce_add_sync(0xffffffffu, cnt);
        if (cnt >= KTOP) prefix = test;
    }

    #pragma unroll
    for (int i = 0; i < 16; i++) {
        int d = lid + 32 * i;
        Qout[d * 17 + m] = (key[i] >= prefix) ? qv[i] : 0.f;
    }
    __syncthreads();

    float* ob = out + (size_t)row * (512 * 16);
    #pragma unroll
    for (int i = 0; i < 16; i++) {
        int e = tid + 512 * i;
        ob[e] = Qout[(e >> 4) * 17 + (e & 15)];
    }
}

// ============================================================
extern "C" void kernel_launch(void* const* d_in, const int* in_sizes, int n_in,
                              void* d_out, int out_size) {
    const float* F    = (const float*)d_in[0];
    const float* Wqkv = (const float*)d_in[1];
    const float* bqkv = (const float*)d_in[2];
    const float* Wout = (const float*)d_in[3];
    const float* bout = (const float*)d_in[4];
    const float* w1   = (const float*)d_in[5];
    const float* b1   = (const float*)d_in[6];
    const float* lng  = (const float*)d_in[7];
    const float* lnb  = (const float*)d_in[8];
    const float* w2   = (const float*)d_in[9];
    const float* b2   = (const float*)d_in[10];
    const float* tmpl = (const float*)d_in[11];
    float* out = (float*)d_out;

    __nv_bfloat16 *qhi, *qlo;
    float *attn, *fenh, *hbuf, *comp;
    cudaGetSymbolAddress((void**)&qhi,  g_qhi);
    cudaGetSymbolAddress((void**)&qlo,  g_qlo);
    cudaGetSymbolAddress((void**)&attn, g_attn);
    cudaGetSymbolAddress((void**)&fenh, g_fenh);
    cudaGetSymbolAddress((void**)&hbuf, g_h);
    cudaGetSymbolAddress((void**)&comp, g_comp);

    cudaFuncSetAttribute(sgemm_tc, cudaFuncAttributeMaxDynamicSharedMemorySize,
                         GEMM_SMEM);
    cudaFuncSetAttribute(attn_tc, cudaFuncAttributeMaxDynamicSharedMemorySize,
                         ATTN_SMEM);

    // qkv GEMM -> pre-split bf16 hi/lo (Q scaled by 1/8); no fp32 output
    sgemm_tc<<<dim3(1536 / 128, BN / 128), 256, GEMM_SMEM>>>(
        F, Wqkv, bqkv, nullptr, nullptr, qhi, qlo, 1, 512, 1536);
    attn_tc<<<dim3(Nn / 64, Bb * Hh), 128, ATTN_SMEM>>>(qhi, qlo, attn);
    sgemm_tc<<<dim3(512 / 128, BN / 128), 256, GEMM_SMEM>>>(
        attn, Wout, bout, F, fenh, nullptr, nullptr, 0, 512, 512);
    sgemm_tc<<<dim3(512 / 128, BN / 128), 256, GEMM_SMEM>>>(
        fenh, w1, b1, nullptr, hbuf, nullptr, nullptr, 0, 512, 512);
    ln_gelu_comp_kernel<<<BN, 256>>>(hbuf, lng, lnb, w2, b2, comp);
    outer_topk_kernel<<<BN, 512>>>(F, tmpl, comp, out);
}